// round 15
// baseline (speedup 1.0000x reference)
#include <cuda_runtime.h>
#include <cuda_bf16.h>
#include <math.h>
#include <stdint.h>

#define BB 2
#define LL 4096
#define DD 1024
#define TOK (BB*LL)        // 8192
#define HTOK (TOK/2)       // 4096
#define NH 16
#define HD 64
#define WIN 256
#define NE 8
#define FFH 4096
#define MAXTILE 136

// ---------------- scratch (static device memory, no runtime alloc) ----------
__device__ float g_xln[(size_t)TOK*DD];               // fp32 LN out (gate reads; LN3 only)
__device__ __nv_bfloat16 g_xh[(size_t)TOK*DD];        // split LN out
__device__ __nv_bfloat16 g_xl[(size_t)TOK*DD];
__device__ __nv_bfloat16 g_qkvh[(size_t)TOK*3*DD];    // split qkv (hi)
__device__ __nv_bfloat16 g_qkvl[(size_t)TOK*3*DD];    // split qkv (lo)
__device__ __nv_bfloat16 g_ah[(size_t)TOK*DD];        // split attention out
__device__ __nv_bfloat16 g_al[(size_t)TOK*DD];
__device__ float g_x[(size_t)TOK*DD];                 // running residual (fp32)
__device__ __nv_bfloat16 g_xrh[(size_t)TOK*DD];       // split post-MoE residual
__device__ __nv_bfloat16 g_xrl[(size_t)TOK*DD];
__device__ float g_moey[(size_t)NE*TOK*DD];
__device__ __nv_bfloat16 g_hh[(size_t)TOK*FFH];       // split FF hidden
__device__ __nv_bfloat16 g_hl[(size_t)TOK*FFH];
__device__ int2   g_topi[TOK];
__device__ float2 g_topw[TOK];
__device__ float  g_ent[TOK];

// sparse MoE routing state
__device__ int g_cnt[NE];
__device__ int g_idxflat[NE*TOK];
__device__ int g_pos[2*TOK];
__device__ int g_tile_rb[MAXTILE];
__device__ int g_tile_cnt[MAXTILE];
__device__ int g_tile_e[MAXTILE];
__device__ int g_ntiles;

// transposed + split bf16 weights  [N][K] layout
#define OFF_QKV  0u
#define OFF_ATT  3145728u
#define OFF_CONV 4194304u
#define OFF_EXP  7340032u
#define OFF_FF1  15728640u
#define OFF_FF2  19922944u
#define WT_TOTAL 24117248u
__device__ __nv_bfloat16 g_wh[WT_TOTAL];
__device__ __nv_bfloat16 g_wl[WT_TOTAL];

__device__ __forceinline__ float gelu_exact(float x) {
    return 0.5f * x * (1.0f + erff(x * 0.70710678118654752f));
}

__device__ __forceinline__ uint32_t smem_u32(const void* p) {
    uint32_t a;
    asm("{ .reg .u64 t; cvta.to.shared.u64 t, %1; cvt.u32.u64 %0, t; }" : "=r"(a) : "l"(p));
    return a;
}

__device__ __forceinline__ void ldm_x4(uint32_t* r, uint32_t addr) {
    asm volatile("ldmatrix.sync.aligned.m8n8.x4.shared.b16 {%0,%1,%2,%3}, [%4];"
                 : "=r"(r[0]), "=r"(r[1]), "=r"(r[2]), "=r"(r[3]) : "r"(addr));
}

__device__ __forceinline__ void ldm_x4_t(uint32_t* r, uint32_t addr) {
    asm volatile("ldmatrix.sync.aligned.m8n8.x4.trans.shared.b16 {%0,%1,%2,%3}, [%4];"
                 : "=r"(r[0]), "=r"(r[1]), "=r"(r[2]), "=r"(r[3]) : "r"(addr));
}

__device__ __forceinline__ void mma_bf16(float* d, const uint32_t* a, const uint32_t* b) {
    asm volatile(
        "mma.sync.aligned.m16n8k16.row.col.f32.bf16.bf16.f32 "
        "{%0,%1,%2,%3}, {%4,%5,%6,%7}, {%8,%9}, {%0,%1,%2,%3};"
        : "+f"(d[0]), "+f"(d[1]), "+f"(d[2]), "+f"(d[3])
        : "r"(a[0]), "r"(a[1]), "r"(a[2]), "r"(a[3]), "r"(b[0]), "r"(b[1]));
}

#define CP16(dst, src) \
    asm volatile("cp.async.cg.shared.global [%0], [%1], 16;" :: "r"(dst), "l"(src))
#define CP16Z(dst, src, sz) \
    asm volatile("cp.async.cg.shared.global [%0], [%1], 16, %2;" :: "r"(dst), "l"(src), "r"(sz))
#define CP_COMMIT() asm volatile("cp.async.commit_group;" ::: "memory")
#define CP_WAIT(n)  asm volatile("cp.async.wait_group %0;" :: "n"(n) : "memory")

__device__ __forceinline__ void split2(float a, float b, uint32_t& hi, uint32_t& lo) {
    __nv_bfloat16 ha = __float2bfloat16_rn(a), hb = __float2bfloat16_rn(b);
    float ra = a - __bfloat162float(ha), rb = b - __bfloat162float(hb);
    __nv_bfloat16 la = __float2bfloat16_rn(ra), lb = __float2bfloat16_rn(rb);
    hi = (uint32_t)__bfloat16_as_ushort(ha) | ((uint32_t)__bfloat16_as_ushort(hb) << 16);
    lo = (uint32_t)__bfloat16_as_ushort(la) | ((uint32_t)__bfloat16_as_ushort(lb) << 16);
}

// ---------------- shared GEMM machinery (R9 proven config) -----------------------
// 128x128 tile, 8 warps (2x4), warp tile 64x32, K-chunk 32, 2-stage, 2 CTA/SM.
#define ROWB   80
#define ASZ    10240          // 128 * 80
#define STAGE  40960          // A_h + A_l + B_h + B_l
#define GEMM_SMEM (2 * STAGE) // 81920

struct GemmCtx {
    uint32_t sb, foff, aoff, boff;
    int lane, wm, wn, frow, fhalf;
};

__device__ __forceinline__ void gemm_setup(GemmCtx& g, char* sm) {
    const int tid = threadIdx.x;
    g.sb = smem_u32(sm);
    g.lane = tid & 31;
    const int wid = tid >> 5;
    g.wm = wid >> 2; g.wn = wid & 3;
    g.frow = tid >> 1; g.fhalf = tid & 1;
    g.foff = (uint32_t)(g.frow * ROWB + g.fhalf * 32);
    g.aoff = (uint32_t)((g.wm * 64 + (g.lane & 15)) * ROWB + (g.lane >> 4) * 16);
    const int bgroup = g.lane >> 3, bwithin = g.lane & 7;
    g.boff = (uint32_t)((g.wn * 32 + (bgroup >> 1) * 8 + bwithin) * ROWB + (bgroup & 1) * 16);
}

__device__ __forceinline__ void cp_pair(uint32_t dst_h, uint32_t dst_l,
                                        const __nv_bfloat16* src_h,
                                        const __nv_bfloat16* src_l) {
    CP16(dst_h,      (const char*)src_h);
    CP16(dst_h + 16, (const char*)src_h + 16);
    CP16(dst_l,      (const char*)src_l);
    CP16(dst_l + 16, (const char*)src_l + 16);
}

__device__ __forceinline__ void compute_stage(const GemmCtx& g, int buf,
                                              float acc[4][4][4]) {
    const uint32_t sA_h = g.sb + buf * STAGE;
    const uint32_t sA_l = sA_h + ASZ;
    const uint32_t sB_h = sA_h + 2 * ASZ;
    const uint32_t sB_l = sA_h + 3 * ASZ;
    #pragma unroll
    for (int ks = 0; ks < 2; ks++) {
        uint32_t Ah[4][4], Al[4][4], Bhf[4][2], Blf[4][2];
        #pragma unroll
        for (int mt = 0; mt < 4; mt++) {
            ldm_x4(Ah[mt], sA_h + g.aoff + mt * (16 * ROWB) + ks * 32);
            ldm_x4(Al[mt], sA_l + g.aoff + mt * (16 * ROWB) + ks * 32);
        }
        #pragma unroll
        for (int n2 = 0; n2 < 2; n2++) {
            uint32_t r[4];
            ldm_x4(r, sB_h + g.boff + n2 * (16 * ROWB) + ks * 32);
            Bhf[n2*2][0] = r[0]; Bhf[n2*2][1] = r[1];
            Bhf[n2*2+1][0] = r[2]; Bhf[n2*2+1][1] = r[3];
            ldm_x4(r, sB_l + g.boff + n2 * (16 * ROWB) + ks * 32);
            Blf[n2*2][0] = r[0]; Blf[n2*2][1] = r[1];
            Blf[n2*2+1][0] = r[2]; Blf[n2*2+1][1] = r[3];
        }
        #pragma unroll
        for (int mt = 0; mt < 4; mt++)
            #pragma unroll
            for (int nt = 0; nt < 4; nt++) {
                mma_bf16(acc[mt][nt], Ah[mt], Bhf[nt]);
                mma_bf16(acc[mt][nt], Ah[mt], Blf[nt]);
                mma_bf16(acc[mt][nt], Al[mt], Bhf[nt]);
            }
    }
}

// ---------------- standard GEMM ---------------------------------------------------
template<bool GELU, bool RESID, bool OSPLIT>
__global__ void __launch_bounds__(256, 2) gemm_mma(const __nv_bfloat16* __restrict__ Ah,
                                                   const __nv_bfloat16* __restrict__ Al,
                                                   const __nv_bfloat16* __restrict__ Bh,
                                                   const __nv_bfloat16* __restrict__ Bl,
                                                   const float* __restrict__ bias,
                                                   const float* __restrict__ R,
                                                   float* __restrict__ C,
                                                   __nv_bfloat16* __restrict__ Oh,
                                                   __nv_bfloat16* __restrict__ Ol,
                                                   int M, int N, int K) {
    extern __shared__ char sm[];
    GemmCtx g; gemm_setup(g, sm);
    const int bm = blockIdx.y * 128, bn = blockIdx.x * 128;

    const __nv_bfloat16* Ahp = Ah + (size_t)(bm + g.frow) * K + g.fhalf * 16;
    const __nv_bfloat16* Alp = Al + (size_t)(bm + g.frow) * K + g.fhalf * 16;
    const __nv_bfloat16* Bhp = Bh + (size_t)(bn + g.frow) * K + g.fhalf * 16;
    const __nv_bfloat16* Blp = Bl + (size_t)(bn + g.frow) * K + g.fhalf * 16;

    float acc[4][4][4] = {};
    const int nst = K >> 5;

    auto issue = [&](int s, int buf) {
        const int k0 = s << 5;
        const uint32_t base = g.sb + buf * STAGE;
        cp_pair(base + g.foff,         base + ASZ + g.foff,   Ahp + k0, Alp + k0);
        cp_pair(base + 2*ASZ + g.foff, base + 3*ASZ + g.foff, Bhp + k0, Blp + k0);
        CP_COMMIT();
    };

    issue(0, 0);
    for (int s = 0; s < nst; s++) {
        const int buf = s & 1;
        if (s + 1 < nst) { issue(s + 1, buf ^ 1); CP_WAIT(1); }
        else             { CP_WAIT(0); }
        __syncthreads();
        compute_stage(g, buf, acc);
        __syncthreads();
    }

    const int r0base = bm + g.wm * 64 + (g.lane >> 2);
    const int cbase = bn + g.wn * 32 + (g.lane & 3) * 2;
    #pragma unroll
    for (int mt = 0; mt < 4; mt++) {
        #pragma unroll
        for (int nt = 0; nt < 4; nt++) {
            const int c = cbase + nt * 8;
            const float2 bb = *(const float2*)(bias + c);
            const int r0 = r0base + mt * 16;
            const int r1 = r0 + 8;
            float2 v0, v1;
            v0.x = acc[mt][nt][0] + bb.x; v0.y = acc[mt][nt][1] + bb.y;
            v1.x = acc[mt][nt][2] + bb.x; v1.y = acc[mt][nt][3] + bb.y;
            if (GELU) {
                v0.x = gelu_exact(v0.x); v0.y = gelu_exact(v0.y);
                v1.x = gelu_exact(v1.x); v1.y = gelu_exact(v1.y);
            }
            if (RESID) {
                const float2 q0 = *(const float2*)(R + (size_t)r0 * N + c);
                const float2 q1 = *(const float2*)(R + (size_t)r1 * N + c);
                v0.x += q0.x; v0.y += q0.y; v1.x += q1.x; v1.y += q1.y;
            }
            if (OSPLIT) {
                uint32_t h0, l0, h1, l1;
                split2(v0.x, v0.y, h0, l0);
                split2(v1.x, v1.y, h1, l1);
                *(uint32_t*)(Oh + (size_t)r0 * N + c) = h0;
                *(uint32_t*)(Ol + (size_t)r0 * N + c) = l0;
                *(uint32_t*)(Oh + (size_t)r1 * N + c) = h1;
                *(uint32_t*)(Ol + (size_t)r1 * N + c) = l1;
            } else {
                *(float2*)(C + (size_t)r0 * N + c) = v0;
                *(float2*)(C + (size_t)r1 * N + c) = v1;
            }
        }
    }
}

// ---------------- conv GEMM with fused dilated im2col gather -------------------
__global__ void __launch_bounds__(256, 2) gemm_conv(const __nv_bfloat16* __restrict__ xh,
                                                    const __nv_bfloat16* __restrict__ xl,
                                                    const __nv_bfloat16* __restrict__ Bh,
                                                    const __nv_bfloat16* __restrict__ Bl,
                                                    const float* __restrict__ bias,
                                                    float* __restrict__ C) {
    extern __shared__ char sm[];
    GemmCtx g; gemm_setup(g, sm);
    const int bm = blockIdx.y * 128, bn = blockIdx.x * 128;
    const int N = DD, K = 3 * DD;

    const int t = bm + g.frow;
    const int b = t >> 12, l = t & (LL - 1);
    const __nv_bfloat16* Bhp = Bh + (size_t)(bn + g.frow) * K + g.fhalf * 16;
    const __nv_bfloat16* Blp = Bl + (size_t)(bn + g.frow) * K + g.fhalf * 16;

    float acc[4][4][4] = {};
    const int nst = K >> 5;  // 96

    auto issue = [&](int s, int buf) {
        const int k0 = s << 5;
        const uint32_t base = g.sb + buf * STAGE;
        const int kk = k0 + g.fhalf * 16;
        const int tap = kk >> 10, din = kk & 1023;
        const int ls = l + 2 * tap - 2;
        const int ok = ((unsigned)ls < (unsigned)LL) ? 16 : 0;
        const int lsc = min(max(ls, 0), LL - 1);
        const size_t abase = ((size_t)(b * LL + lsc)) * DD + din;
        const char* sah = (const char*)(xh + abase);
        const char* sal = (const char*)(xl + abase);
        CP16Z(base + g.foff,            sah,      ok);
        CP16Z(base + g.foff + 16,       sah + 16, ok);
        CP16Z(base + ASZ + g.foff,      sal,      ok);
        CP16Z(base + ASZ + g.foff + 16, sal + 16, ok);
        cp_pair(base + 2*ASZ + g.foff, base + 3*ASZ + g.foff, Bhp + k0, Blp + k0);
        CP_COMMIT();
    };

    issue(0, 0);
    for (int s = 0; s < nst; s++) {
        const int buf = s & 1;
        if (s + 1 < nst) { issue(s + 1, buf ^ 1); CP_WAIT(1); }
        else             { CP_WAIT(0); }
        __syncthreads();
        compute_stage(g, buf, acc);
        __syncthreads();
    }

    const int r0base = bm + g.wm * 64 + (g.lane >> 2);
    const int cbase = bn + g.wn * 32 + (g.lane & 3) * 2;
    #pragma unroll
    for (int mt = 0; mt < 4; mt++) {
        #pragma unroll
        for (int nt = 0; nt < 4; nt++) {
            const int c = cbase + nt * 8;
            const float2 bb = *(const float2*)(bias + c);
            const int r0 = r0base + mt * 16;
            const int r1 = r0 + 8;
            const float2 q0 = *(const float2*)(C + (size_t)r0 * N + c);
            const float2 q1 = *(const float2*)(C + (size_t)r1 * N + c);
            float2 v0, v1;
            v0.x = acc[mt][nt][0] + bb.x + q0.x; v0.y = acc[mt][nt][1] + bb.y + q0.y;
            v1.x = acc[mt][nt][2] + bb.x + q1.x; v1.y = acc[mt][nt][3] + bb.y + q1.y;
            *(float2*)(C + (size_t)r0 * N + c) = v0;
            *(float2*)(C + (size_t)r1 * N + c) = v1;
        }
    }
}

// ---------------- sparse MoE grouped GEMM ---------------------------------------
__global__ void __launch_bounds__(256, 2) gemm_moe(const __nv_bfloat16* __restrict__ xh,
                                                   const __nv_bfloat16* __restrict__ xl,
                                                   const __nv_bfloat16* __restrict__ WhBase,
                                                   const __nv_bfloat16* __restrict__ WlBase,
                                                   const float* __restrict__ ebias,
                                                   float* __restrict__ Y) {
    if ((int)blockIdx.y >= g_ntiles) return;
    extern __shared__ char sm[];
    GemmCtx g; gemm_setup(g, sm);
    const int rb = g_tile_rb[blockIdx.y];
    const int tcnt = g_tile_cnt[blockIdx.y];
    const int e = g_tile_e[blockIdx.y];
    const int bn = blockIdx.x * 128;
    const int N = DD, K = DD;

    const int tok = g_idxflat[rb + g.frow];
    const __nv_bfloat16* Ahp = xh + (size_t)tok * K + g.fhalf * 16;
    const __nv_bfloat16* Alp = xl + (size_t)tok * K + g.fhalf * 16;
    const __nv_bfloat16* Bhp = WhBase + (size_t)e * DD * DD + (size_t)(bn + g.frow) * K + g.fhalf * 16;
    const __nv_bfloat16* Blp = WlBase + (size_t)e * DD * DD + (size_t)(bn + g.frow) * K + g.fhalf * 16;
    const float* bias = ebias + (size_t)e * DD;

    float acc[4][4][4] = {};
    const int nst = K >> 5;

    auto issue = [&](int s, int buf) {
        const int k0 = s << 5;
        const uint32_t base = g.sb + buf * STAGE;
        cp_pair(base + g.foff,         base + ASZ + g.foff,   Ahp + k0, Alp + k0);
        cp_pair(base + 2*ASZ + g.foff, base + 3*ASZ + g.foff, Bhp + k0, Blp + k0);
        CP_COMMIT();
    };

    issue(0, 0);
    for (int s = 0; s < nst; s++) {
        const int buf = s & 1;
        if (s + 1 < nst) { issue(s + 1, buf ^ 1); CP_WAIT(1); }
        else             { CP_WAIT(0); }
        __syncthreads();
        compute_stage(g, buf, acc);
        __syncthreads();
    }

    const int lrbase = g.wm * 64 + (g.lane >> 2);
    const int cbase = bn + g.wn * 32 + (g.lane & 3) * 2;
    #pragma unroll
    for (int mt = 0; mt < 4; mt++) {
        #pragma unroll
        for (int nt = 0; nt < 4; nt++) {
            const int c = cbase + nt * 8;
            const float2 bb = *(const float2*)(bias + c);
            const int lr0 = lrbase + mt * 16;
            const int lr1 = lr0 + 8;
            float2 v0, v1;
            v0.x = gelu_exact(acc[mt][nt][0] + bb.x);
            v0.y = gelu_exact(acc[mt][nt][1] + bb.y);
            v1.x = gelu_exact(acc[mt][nt][2] + bb.x);
            v1.y = gelu_exact(acc[mt][nt][3] + bb.y);
            if (lr0 < tcnt) *(float2*)(Y + (size_t)(rb + lr0) * N + c) = v0;
            if (lr1 < tcnt) *(float2*)(Y + (size_t)(rb + lr1) * N + c) = v1;
        }
    }
}

// ---------------- tensor-core windowed flash attention --------------------------
// Pointers are pre-offset per batch half; grid covers 16 windows x 16 heads.
#define AROWB 144
__global__ void __launch_bounds__(256) attn_tc(const __nv_bfloat16* __restrict__ qh,
                                               const __nv_bfloat16* __restrict__ ql,
                                               __nv_bfloat16* __restrict__ oh,
                                               __nv_bfloat16* __restrict__ ol) {
    __shared__ char smn[4 * 32 * AROWB];   // Kh, Kl, Vh, Vl (32 x 144B each)
    const int h = blockIdx.x & 15;
    const int w = (blockIdx.x >> 4) & 15;
    const int b = blockIdx.x >> 8;         // 0 for half-grid launches
    const int t0 = b * LL + w * WIN;
    const int tid = threadIdx.x, lane = tid & 31, wid = tid >> 5;
    const int gid = lane >> 2, tig = lane & 3;
    const uint32_t sb = smem_u32(smn);
    const uint32_t sKh = sb, sKl = sb + 4608, sVh = sb + 9216, sVl = sb + 13824;

    uint32_t Qh[2][4][4], Ql[2][4][4];
    #pragma unroll
    for (int mt = 0; mt < 2; mt++) {
        const int r0 = t0 + wid * 32 + mt * 16 + gid;
        const size_t q0 = (size_t)r0 * 3072 + h * 64;
        const size_t q1 = q0 + (size_t)8 * 3072;
        #pragma unroll
        for (int kk = 0; kk < 4; kk++) {
            const int c = kk * 16 + 2 * tig;
            Qh[mt][kk][0] = *(const uint32_t*)(qh + q0 + c);
            Ql[mt][kk][0] = *(const uint32_t*)(ql + q0 + c);
            Qh[mt][kk][1] = *(const uint32_t*)(qh + q1 + c);
            Ql[mt][kk][1] = *(const uint32_t*)(ql + q1 + c);
            Qh[mt][kk][2] = *(const uint32_t*)(qh + q0 + c + 8);
            Ql[mt][kk][2] = *(const uint32_t*)(ql + q0 + c + 8);
            Qh[mt][kk][3] = *(const uint32_t*)(qh + q1 + c + 8);
            Ql[mt][kk][3] = *(const uint32_t*)(ql + q1 + c + 8);
        }
    }

    float o[2][8][4] = {};
    float mrun[2][2] = {{-1e30f, -1e30f}, {-1e30f, -1e30f}};
    float lrun[2][2] = {};

    const int stok = tid >> 3, sq = tid & 7;
    const size_t kvoff = (size_t)(t0 + stok) * 3072 + 1024 + h * 64 + sq * 8;
    const uint32_t soff = (uint32_t)(stok * AROWB + sq * 16);

    const uint32_t kaddr = (uint32_t)((((lane >> 4) & 1) * 8 + (lane & 7)) * AROWB
                                      + ((lane >> 3) & 1) * 16);

    for (int c8 = 0; c8 < 8; c8++) {
        __syncthreads();
        {
            const size_t kbase = kvoff + (size_t)(c8 * 32) * 3072;
            *(uint4*)(smn + soff)         = *(const uint4*)(qh + kbase);
            *(uint4*)(smn + 4608 + soff)  = *(const uint4*)(ql + kbase);
            *(uint4*)(smn + 9216 + soff)  = *(const uint4*)(qh + kbase + 1024);
            *(uint4*)(smn + 13824 + soff) = *(const uint4*)(ql + kbase + 1024);
        }
        __syncthreads();

        float s[2][4][4] = {};
        #pragma unroll
        for (int kk = 0; kk < 4; kk++) {
            #pragma unroll
            for (int n2 = 0; n2 < 2; n2++) {
                uint32_t rbh[4], rbl[4];
                const uint32_t a = kaddr + (uint32_t)(n2 * 16 * AROWB + kk * 32);
                ldm_x4(rbh, sKh + a);
                ldm_x4(rbl, sKl + a);
                #pragma unroll
                for (int mt = 0; mt < 2; mt++) {
                    mma_bf16(s[mt][n2*2],   Qh[mt][kk], rbh);
                    mma_bf16(s[mt][n2*2],   Qh[mt][kk], rbl);
                    mma_bf16(s[mt][n2*2],   Ql[mt][kk], rbh);
                    mma_bf16(s[mt][n2*2+1], Qh[mt][kk], rbh + 2);
                    mma_bf16(s[mt][n2*2+1], Qh[mt][kk], rbl + 2);
                    mma_bf16(s[mt][n2*2+1], Ql[mt][kk], rbh + 2);
                }
            }
        }

        uint32_t Ph[2][2][4], Pl[2][2][4];
        #pragma unroll
        for (int mt = 0; mt < 2; mt++) {
            float m0 = -1e30f, m1 = -1e30f;
            #pragma unroll
            for (int nt = 0; nt < 4; nt++) {
                #pragma unroll
                for (int i = 0; i < 4; i++) s[mt][nt][i] *= 0.125f;
                m0 = fmaxf(m0, fmaxf(s[mt][nt][0], s[mt][nt][1]));
                m1 = fmaxf(m1, fmaxf(s[mt][nt][2], s[mt][nt][3]));
            }
            m0 = fmaxf(m0, __shfl_xor_sync(0xffffffffu, m0, 1));
            m0 = fmaxf(m0, __shfl_xor_sync(0xffffffffu, m0, 2));
            m1 = fmaxf(m1, __shfl_xor_sync(0xffffffffu, m1, 1));
            m1 = fmaxf(m1, __shfl_xor_sync(0xffffffffu, m1, 2));
            const float mn0 = fmaxf(mrun[mt][0], m0);
            const float mn1 = fmaxf(mrun[mt][1], m1);
            const float f0 = __expf(mrun[mt][0] - mn0);
            const float f1 = __expf(mrun[mt][1] - mn1);
            mrun[mt][0] = mn0; mrun[mt][1] = mn1;
            float l0 = 0.f, l1 = 0.f;
            #pragma unroll
            for (int nt = 0; nt < 4; nt++) {
                s[mt][nt][0] = __expf(s[mt][nt][0] - mn0);
                s[mt][nt][1] = __expf(s[mt][nt][1] - mn0);
                s[mt][nt][2] = __expf(s[mt][nt][2] - mn1);
                s[mt][nt][3] = __expf(s[mt][nt][3] - mn1);
                l0 += s[mt][nt][0] + s[mt][nt][1];
                l1 += s[mt][nt][2] + s[mt][nt][3];
            }
            l0 += __shfl_xor_sync(0xffffffffu, l0, 1);
            l0 += __shfl_xor_sync(0xffffffffu, l0, 2);
            l1 += __shfl_xor_sync(0xffffffffu, l1, 1);
            l1 += __shfl_xor_sync(0xffffffffu, l1, 2);
            lrun[mt][0] = lrun[mt][0] * f0 + l0;
            lrun[mt][1] = lrun[mt][1] * f1 + l1;
            #pragma unroll
            for (int nt = 0; nt < 8; nt++) {
                o[mt][nt][0] *= f0; o[mt][nt][1] *= f0;
                o[mt][nt][2] *= f1; o[mt][nt][3] *= f1;
            }
            #pragma unroll
            for (int kk2 = 0; kk2 < 2; kk2++) {
                split2(s[mt][2*kk2][0],   s[mt][2*kk2][1],   Ph[mt][kk2][0], Pl[mt][kk2][0]);
                split2(s[mt][2*kk2][2],   s[mt][2*kk2][3],   Ph[mt][kk2][1], Pl[mt][kk2][1]);
                split2(s[mt][2*kk2+1][0], s[mt][2*kk2+1][1], Ph[mt][kk2][2], Pl[mt][kk2][2]);
                split2(s[mt][2*kk2+1][2], s[mt][2*kk2+1][3], Ph[mt][kk2][3], Pl[mt][kk2][3]);
            }
        }

        #pragma unroll
        for (int dp = 0; dp < 4; dp++) {
            #pragma unroll
            for (int kk2 = 0; kk2 < 2; kk2++) {
                uint32_t vbh[4], vbl[4];
                const uint32_t va = (uint32_t)((kk2 * 16 + (lane & 7) + ((lane >> 3) & 1) * 8) * AROWB
                                               + (dp * 2 + ((lane >> 4) & 1)) * 16);
                ldm_x4_t(vbh, sVh + va);
                ldm_x4_t(vbl, sVl + va);
                #pragma unroll
                for (int mt = 0; mt < 2; mt++) {
                    mma_bf16(o[mt][dp*2],   Ph[mt][kk2], vbh);
                    mma_bf16(o[mt][dp*2],   Ph[mt][kk2], vbl);
                    mma_bf16(o[mt][dp*2],   Pl[mt][kk2], vbh);
                    mma_bf16(o[mt][dp*2+1], Ph[mt][kk2], vbh + 2);
                    mma_bf16(o[mt][dp*2+1], Ph[mt][kk2], vbl + 2);
                    mma_bf16(o[mt][dp*2+1], Pl[mt][kk2], vbh + 2);
                }
            }
        }
    }

    #pragma unroll
    for (int mt = 0; mt < 2; mt++) {
        const float i0 = 1.f / lrun[mt][0], i1 = 1.f / lrun[mt][1];
        const int r0 = t0 + wid * 32 + mt * 16 + gid;
        #pragma unroll
        for (int nt = 0; nt < 8; nt++) {
            const int c = h * 64 + nt * 8 + 2 * tig;
            uint32_t ph, pl;
            split2(o[mt][nt][0] * i0, o[mt][nt][1] * i0, ph, pl);
            *(uint32_t*)(oh + (size_t)r0 * 1024 + c) = ph;
            *(uint32_t*)(ol + (size_t)r0 * 1024 + c) = pl;
            split2(o[mt][nt][2] * i1, o[mt][nt][3] * i1, ph, pl);
            *(uint32_t*)(oh + (size_t)(r0 + 8) * 1024 + c) = ph;
            *(uint32_t*)(ol + (size_t)(r0 + 8) * 1024 + c) = pl;
        }
    }
}

// ---------------- weight transpose + bf16 split ---------------------------------
__global__ void __launch_bounds__(256) wt_kernel(const float* __restrict__ W,
                                                 __nv_bfloat16* __restrict__ Th,
                                                 __nv_bfloat16* __restrict__ Tl,
                                                 int K, int N) {
    __shared__ float tile[32][33];
    const size_t slab = (size_t)blockIdx.z * K * N;
    const int k0 = blockIdx.y * 32, n0 = blockIdx.x * 32;
    const int x = threadIdx.x, y = threadIdx.y;
    #pragma unroll
    for (int j = 0; j < 32; j += 8)
        tile[y + j][x] = W[slab + (size_t)(k0 + y + j) * N + n0 + x];
    __syncthreads();
    #pragma unroll
    for (int j = 0; j < 32; j += 8) {
        const float v = tile[x][y + j];
        const int n = n0 + y + j, k = k0 + x;
        const __nv_bfloat16 h = __float2bfloat16_rn(v);
        Th[slab + (size_t)n * K + k] = h;
        Tl[slab + (size_t)n * K + k] = __float2bfloat16_rn(v - __bfloat162float(h));
    }
}

__global__ void __launch_bounds__(256) convw_t(const float* __restrict__ cw,
                                               __nv_bfloat16* __restrict__ Th,
                                               __nv_bfloat16* __restrict__ Tl) {
    const size_t idx = (size_t)blockIdx.x * 256 + threadIdx.x;
    const int dout = (int)(idx / 3072);
    const int r = (int)(idx % 3072);
    const int tap = r >> 10, din = r & 1023;
    const float v = cw[((size_t)dout * DD + din) * 3 + tap];
    const __nv_bfloat16 h = __float2bfloat16_rn(v);
    Th[idx] = h;
    Tl[idx] = __float2bfloat16_rn(v - __bfloat162float(h));
}

// ---------------- LayerNorm (optional fp32 + split bf16 outputs) -----------------
__global__ void __launch_bounds__(256) ln_kernel(const float* __restrict__ x,
                                                 const float* __restrict__ g,
                                                 const float* __restrict__ b,
                                                 float* __restrict__ y,
                                                 __nv_bfloat16* __restrict__ yh,
                                                 __nv_bfloat16* __restrict__ yl) {
    __shared__ float red[8];
    __shared__ float sh_mu, sh_inv;
    const int tid = threadIdx.x, lane = tid & 31, warp = tid >> 5;
    const float4 xv = ((const float4*)(x + (size_t)blockIdx.x * DD))[tid];

    float s = xv.x + xv.y + xv.z + xv.w;
    #pragma unroll
    for (int o = 16; o > 0; o >>= 1) s += __shfl_down_sync(0xffffffffu, s, o);
    if (lane == 0) red[warp] = s;
    __syncthreads();
    if (tid == 0) {
        float t = 0.f;
        #pragma unroll
        for (int i = 0; i < 8; i++) t += red[i];
        sh_mu = t * (1.0f / DD);
    }
    __syncthreads();
    const float mu = sh_mu;
    const float dx = xv.x - mu, dy = xv.y - mu, dz = xv.z - mu, dw = xv.w - mu;
    float s2 = dx*dx + dy*dy + dz*dz + dw*dw;
    #pragma unroll
    for (int o = 16; o > 0; o >>= 1) s2 += __shfl_down_sync(0xffffffffu, s2, o);
    if (lane == 0) red[warp] = s2;
    __syncthreads();
    if (tid == 0) {
        float t = 0.f;
        #pragma unroll
        for (int i = 0; i < 8; i++) t += red[i];
        sh_inv = rsqrtf(t * (1.0f / DD) + 1e-5f);
    }
    __syncthreads();
    const float inv = sh_inv;
    const float4 gv = ((const float4*)g)[tid];
    const float4 bv = ((const float4*)b)[tid];
    float4 o;
    o.x = dx * inv * gv.x + bv.x;
    o.y = dy * inv * gv.y + bv.y;
    o.z = dz * inv * gv.z + bv.z;
    o.w = dw * inv * gv.w + bv.w;
    const size_t idx = (size_t)blockIdx.x * DD + tid * 4;
    if (y) *(float4*)(y + idx) = o;
    uint32_t h0, l0, h1, l1;
    split2(o.x, o.y, h0, l0);
    split2(o.z, o.w, h1, l1);
    *(uint32_t*)(yh + idx)     = h0;
    *(uint32_t*)(yh + idx + 2) = h1;
    *(uint32_t*)(yl + idx)     = l0;
    *(uint32_t*)(yl + idx + 2) = l1;
}

// ---------------- gate: softmax, entropy, top-2 ---------------------------------
__global__ void __launch_bounds__(256) gate_kernel(const float* __restrict__ xln,
                                                   const float* __restrict__ gw,
                                                   const float* __restrict__ gb) {
    if (blockIdx.x == 0 && threadIdx.x < NE) g_cnt[threadIdx.x] = 0;
    const int warp = threadIdx.x >> 5, lane = threadIdx.x & 31;
    const int t = blockIdx.x * 8 + warp;
    const float* xr = xln + (size_t)t * DD;

    float a[8] = {0.f,0.f,0.f,0.f,0.f,0.f,0.f,0.f};
    for (int i = lane; i < DD; i += 32) {
        const float xv = xr[i];
        const float* g8 = gw + i * 8;
        #pragma unroll
        for (int e = 0; e < 8; e++) a[e] += xv * g8[e];
    }
    #pragma unroll
    for (int e = 0; e < 8; e++) {
        #pragma unroll
        for (int o = 16; o > 0; o >>= 1) a[e] += __shfl_down_sync(0xffffffffu, a[e], o);
    }
    if (lane == 0) {
        float lg[8], mx = -1e30f;
        #pragma unroll
        for (int e = 0; e < 8; e++) { lg[e] = a[e] + gb[e]; mx = fmaxf(mx, lg[e]); }
        float p[8], den = 0.f;
        #pragma unroll
        for (int e = 0; e < 8; e++) { p[e] = expf(lg[e] - mx); den += p[e]; }
        float ent = 0.f;
        #pragma unroll
        for (int e = 0; e < 8; e++) { p[e] /= den; ent -= p[e] * logf(p[e] + 1e-10f); }
        g_ent[t] = ent;

        int i0 = 0; float v0 = p[0];
        #pragma unroll
        for (int e = 1; e < 8; e++) if (p[e] > v0) { v0 = p[e]; i0 = e; }
        int i1 = -1; float v1 = -1e30f;
        #pragma unroll
        for (int e = 0; e < 8; e++) if (e != i0 && p[e] > v1) { v1 = p[e]; i1 = e; }
        const float sw = v0 + v1;
        g_topi[t] = make_int2(i0, i1);
        g_topw[t] = make_float2(v0 / sw, v1 / sw);
    }
}

// ---------------- routing kernels -------------------------------------------------
__global__ void __launch_bounds__(256) scatter_kernel() {
    const int t = blockIdx.x * 256 + threadIdx.x;
    if (t >= TOK) return;
    const int2 ii = g_topi[t];
    const int p0 = atomicAdd(&g_cnt[ii.x], 1);
    g_idxflat[ii.x * TOK + p0] = t;
    g_pos[2 * t] = ii.x * TOK + p0;
    const int p1 = atomicAdd(&g_cnt[ii.y], 1);
    g_idxflat[ii.y * TOK + p1] = t;
    g_pos[2 * t + 1] = ii.y * TOK + p1;
}

__global__ void __launch_bounds__(256) tile_build() {
    __shared__ int scnt[NE];
    if (threadIdx.x < NE) scnt[threadIdx.x] = g_cnt[threadIdx.x];
    __syncthreads();
    if (threadIdx.x == 0) {
        int nt = 0;
        for (int e = 0; e < NE; e++) {
            const int c = scnt[e];
            const int t = (c + 127) >> 7;
            for (int i = 0; i < t; i++) {
                g_tile_rb[nt] = e * TOK + i * 128;
                g_tile_cnt[nt] = min(128, c - i * 128);
                g_tile_e[nt] = e;
                nt++;
            }
        }
        g_ntiles = nt;
    }
    for (int j = threadIdx.x; j < NE * 128; j += 256) {
        const int e = j >> 7;
        const int c = scnt[e];
        const int off = c + (j & 127);
        const int lim = ((c + 127) >> 7) << 7;
        if (off < lim) g_idxflat[e * TOK + off] = 0;
    }
}

// ---------------- MoE combine: update fp32 resid + emit split ------------------
__global__ void __launch_bounds__(256) combine_kernel(const float* __restrict__ Y,
                                                      float* __restrict__ x,
                                                      __nv_bfloat16* __restrict__ xh,
                                                      __nv_bfloat16* __restrict__ xl) {
    const int t = blockIdx.x;
    const int d = threadIdx.x * 4;
    const int p0 = g_pos[2 * t], p1 = g_pos[2 * t + 1];
    const float2 ww = g_topw[t];
    const float4 a = *(const float4*)(Y + (size_t)p0 * DD + d);
    const float4 b = *(const float4*)(Y + (size_t)p1 * DD + d);
    const size_t idx = (size_t)t * DD + d;
    float4 xv = *(float4*)(x + idx);
    xv.x += ww.x * a.x + ww.y * b.x;
    xv.y += ww.x * a.y + ww.y * b.y;
    xv.z += ww.x * a.z + ww.y * b.z;
    xv.w += ww.x * a.w + ww.y * b.w;
    *(float4*)(x + idx) = xv;
    uint32_t h0, l0, h1, l1;
    split2(xv.x, xv.y, h0, l0);
    split2(xv.z, xv.w, h1, l1);
    *(uint32_t*)(xh + idx)     = h0;
    *(uint32_t*)(xh + idx + 2) = h1;
    *(uint32_t*)(xl + idx)     = l0;
    *(uint32_t*)(xl + idx + 2) = l1;
}

// ---------------- deterministic entropy reduction -------------------------------
__global__ void __launch_bounds__(256) ent_reduce(float* __restrict__ out) {
    __shared__ float sm[256];
    float s = 0.f;
    for (int i = threadIdx.x; i < TOK; i += 256) s += g_ent[i];
    sm[threadIdx.x] = s;
    __syncthreads();
    #pragma unroll
    for (int o = 128; o > 0; o >>= 1) {
        if (threadIdx.x < o) sm[threadIdx.x] += sm[threadIdx.x + o];
        __syncthreads();
    }
    if (threadIdx.x == 0) out[0] = 0.1f * sm[0] / (float)TOK;
}

// ---------------- launch ----------------------------------------------------------
extern "C" void kernel_launch(void* const* d_in, const int* in_sizes, int n_in,
                              void* d_out, int out_size) {
    const float* x          = (const float*)d_in[0];
    const float* ln1_g      = (const float*)d_in[1];
    const float* ln1_b      = (const float*)d_in[2];
    const float* qkv_w      = (const float*)d_in[3];
    const float* qkv_b      = (const float*)d_in[4];
    const float* attn_out_w = (const float*)d_in[5];
    const float* attn_out_b = (const float*)d_in[6];
    const float* ln2_g      = (const float*)d_in[7];
    const float* ln2_b      = (const float*)d_in[8];
    const float* conv_w     = (const float*)d_in[9];
    const float* conv_b     = (const float*)d_in[10];
    const float* ln3_g      = (const float*)d_in[11];
    const float* ln3_b      = (const float*)d_in[12];
    const float* gate_w     = (const float*)d_in[13];
    const float* gate_b     = (const float*)d_in[14];
    const float* expert_w   = (const float*)d_in[15];
    const float* expert_b   = (const float*)d_in[16];
    const float* ff_w1      = (const float*)d_in[17];
    const float* ff_b1      = (const float*)d_in[18];
    const float* ff_w2      = (const float*)d_in[19];
    const float* ff_b2      = (const float*)d_in[20];
    float* out = (float*)d_out;

    float *xln, *xr, *moey;
    __nv_bfloat16 *wh, *wl, *xh, *xl, *qh, *ql, *ah, *al, *xrh, *xrl, *hh, *hl;
    cudaGetSymbolAddress((void**)&xln,  g_xln);
    cudaGetSymbolAddress((void**)&xr,   g_x);
    cudaGetSymbolAddress((void**)&moey, g_moey);
    cudaGetSymbolAddress((void**)&wh,   g_wh);
    cudaGetSymbolAddress((void**)&wl,   g_wl);
    cudaGetSymbolAddress((void**)&xh,   g_xh);
    cudaGetSymbolAddress((void**)&xl,   g_xl);
    cudaGetSymbolAddress((void**)&qh,   g_qkvh);
    cudaGetSymbolAddress((void**)&ql,   g_qkvl);
    cudaGetSymbolAddress((void**)&ah,   g_ah);
    cudaGetSymbolAddress((void**)&al,   g_al);
    cudaGetSymbolAddress((void**)&xrh,  g_xrh);
    cudaGetSymbolAddress((void**)&xrl,  g_xrl);
    cudaGetSymbolAddress((void**)&hh,   g_hh);
    cudaGetSymbolAddress((void**)&hl,   g_hl);

    cudaFuncSetAttribute(gemm_mma<false, false, true>,  cudaFuncAttributeMaxDynamicSharedMemorySize, GEMM_SMEM);
    cudaFuncSetAttribute(gemm_mma<false, true, false>,  cudaFuncAttributeMaxDynamicSharedMemorySize, GEMM_SMEM);
    cudaFuncSetAttribute(gemm_mma<true, false, true>,   cudaFuncAttributeMaxDynamicSharedMemorySize, GEMM_SMEM);
    cudaFuncSetAttribute(gemm_conv, cudaFuncAttributeMaxDynamicSharedMemorySize, GEMM_SMEM);
    cudaFuncSetAttribute(gemm_moe,  cudaFuncAttributeMaxDynamicSharedMemorySize, GEMM_SMEM);

    const dim3 tblk(32, 8);

    // side stream (created per call; intentionally leaked — kernel_launch runs
    // only for correctness + capture)
    cudaStream_t sw;
    cudaEvent_t ev_fork, ev_qkvw, ev_wt, ev_q1, ev_q2, ev_attn, ev_f1, ev_g1;
    cudaStreamCreateWithFlags(&sw, cudaStreamNonBlocking);
    cudaEventCreateWithFlags(&ev_fork, cudaEventDisableTiming);
    cudaEventCreateWithFlags(&ev_qkvw, cudaEventDisableTiming);
    cudaEventCreateWithFlags(&ev_wt,   cudaEventDisableTiming);
    cudaEventCreateWithFlags(&ev_q1,   cudaEventDisableTiming);
    cudaEventCreateWithFlags(&ev_q2,   cudaEventDisableTiming);
    cudaEventCreateWithFlags(&ev_attn, cudaEventDisableTiming);
    cudaEventCreateWithFlags(&ev_f1,   cudaEventDisableTiming);
    cudaEventCreateWithFlags(&ev_g1,   cudaEventDisableTiming);

    // fork at the very start: weight prep is independent of LN1
    cudaEventRecord(ev_fork, 0);
    cudaStreamWaitEvent(sw, ev_fork, 0);

    // side stream: weight transforms (qkv first — on the critical path)
    wt_kernel<<<dim3(3072/32, 1024/32), tblk, 0, sw>>>(qkv_w, wh + OFF_QKV, wl + OFF_QKV, 1024, 3072);
    cudaEventRecord(ev_qkvw, sw);
    wt_kernel<<<dim3(1024/32, 1024/32), tblk, 0, sw>>>(attn_out_w, wh + OFF_ATT, wl + OFF_ATT, 1024, 1024);
    convw_t<<<(1024*3072)/256, 256, 0, sw>>>(conv_w, wh + OFF_CONV, wl + OFF_CONV);
    wt_kernel<<<dim3(4096/32, 1024/32), tblk, 0, sw>>>(ff_w1, wh + OFF_FF1, wl + OFF_FF1, 1024, 4096);
    wt_kernel<<<dim3(1024/32, 1024/32, NE), tblk, 0, sw>>>(expert_w, wh + OFF_EXP, wl + OFF_EXP, 1024, 1024);
    wt_kernel<<<dim3(1024/32, 4096/32), tblk, 0, sw>>>(ff_w2, wh + OFF_FF2, wl + OFF_FF2, 4096, 1024);
    cudaEventRecord(ev_wt, sw);

    // main: LN1 overlaps wt_qkv; qkv GEMM in two M-halves so attention-h1 can
    // overlap qkv-h2 (batch b only reads its own token rows).
    ln_kernel<<<TOK, 256>>>(x, ln1_g, ln1_b, nullptr, xh, xl);
    cudaStreamWaitEvent(0, ev_qkvw, 0);
    gemm_mma<false, false, true><<<dim3(3072/128, HTOK/128), 256, GEMM_SMEM>>>(
        xh, xl, wh + OFF_QKV, wl + OFF_QKV, qkv_b, nullptr, nullptr, qh, ql,
        HTOK, 3072, 1024);
    cudaEventRecord(ev_q1, 0);
    gemm_mma<false, false, true><<<dim3(3072/128, HTOK/128), 256, GEMM_SMEM>>>(
        xh + (size_t)HTOK*DD, xl + (size_t)HTOK*DD, wh + OFF_QKV, wl + OFF_QKV,
        qkv_b, nullptr, nullptr, qh + (size_t)HTOK*3*DD, ql + (size_t)HTOK*3*DD,
        HTOK, 3072, 1024);
    cudaEventRecord(ev_q2, 0);

    // side stream: attention per batch half (h1 overlaps qkv-h2)
    cudaStreamWaitEvent(sw, ev_q1, 0);
    attn_tc<<<(LL / WIN) * NH, 256, 0, sw>>>(qh, ql, ah, al);
    cudaStreamWaitEvent(sw, ev_q2, 0);
    attn_tc<<<(LL / WIN) * NH, 256, 0, sw>>>(qh + (size_t)HTOK*3*DD, ql + (size_t)HTOK*3*DD,
                                             ah + (size_t)HTOK*DD, al + (size_t)HTOK*DD);
    cudaEventRecord(ev_attn, sw);

    // join attention + remaining weight prep before the proj GEMM
    cudaStreamWaitEvent(0, ev_attn, 0);
    cudaStreamWaitEvent(0, ev_wt, 0);
    gemm_mma<false, true, false><<<dim3(1024/128, TOK/128), 256, GEMM_SMEM>>>(
        ah, al, wh + OFF_ATT, wl + OFF_ATT, attn_out_b, x, xr, nullptr, nullptr,
        TOK, 1024, 1024);

    // 2) LN2 -> dilated conv GEMM (fused im2col gather, +resid in place)
    ln_kernel<<<TOK, 256>>>(xr, ln2_g, ln2_b, nullptr, xh, xl);
    gemm_conv<<<dim3(1024/128, TOK/128), 256, GEMM_SMEM>>>(
        xh, xl, wh + OFF_CONV, wl + OFF_CONV, conv_b, xr);

    // 3) LN3 -> gate -> sparse top-2 MoE -> combine (emits split resid)
    ln_kernel<<<TOK, 256>>>(xr, ln3_g, ln3_b, xln, xh, xl);
    gate_kernel<<<TOK / 8, 256>>>(xln, gate_w, gate_b);
    scatter_kernel<<<TOK / 256, 256>>>();
    tile_build<<<1, 256>>>();
    gemm_moe<<<dim3(1024/128, MAXTILE), 256, GEMM_SMEM>>>(
        xh, xl, wh + OFF_EXP, wl + OFF_EXP, expert_b, moey);
    combine_kernel<<<TOK, 256>>>(moey, xr, xrh, xrl);

    // 4) FF pipeline: FF1h1 -> (FF1h2 || FF2h1) -> FF2h2  (row-disjoint halves)
    gemm_mma<true, false, true><<<dim3(FFH/128, HTOK/128), 256, GEMM_SMEM>>>(
        xrh, xrl, wh + OFF_FF1, wl + OFF_FF1, ff_b1, nullptr, nullptr, hh, hl,
        HTOK, FFH, 1024);
    cudaEventRecord(ev_f1, 0);
    gemm_mma<true, false, true><<<dim3(FFH/128, HTOK/128), 256, GEMM_SMEM>>>(
        xrh + (size_t)HTOK*DD, xrl + (size_t)HTOK*DD, wh + OFF_FF1, wl + OFF_FF1,
        ff_b1, nullptr, nullptr, hh + (size_t)HTOK*FFH, hl + (size_t)HTOK*FFH,
        HTOK, FFH, 1024);

    // side stream: FF2 on rows 0..HTOK-1 overlaps FF1h2
    cudaStreamWaitEvent(sw, ev_f1, 0);
    gemm_mma<false, true, false><<<dim3(1024/128, HTOK/128), 256, GEMM_SMEM, sw>>>(
        hh, hl, wh + OFF_FF2, wl + OFF_FF2, ff_b2, xr, out, nullptr, nullptr,
        HTOK, 1024, FFH);
    cudaEventRecord(ev_g1, sw);

    // main: FF2 on rows HTOK..TOK-1 (depends only on FF1h2, same stream)
    gemm_mma<false, true, false><<<dim3(1024/128, HTOK/128), 256, GEMM_SMEM>>>(
        hh + (size_t)HTOK*FFH, hl + (size_t)HTOK*FFH, wh + OFF_FF2, wl + OFF_FF2,
        ff_b2, xr + (size_t)HTOK*DD, out + (size_t)HTOK*DD, nullptr, nullptr,
        HTOK, 1024, FFH);

    // join side stream, then entropy scalar
    cudaStreamWaitEvent(0, ev_g1, 0);
    ent_reduce<<<1, 256>>>(out + (size_t)TOK * DD);
}

// round 16
// speedup vs baseline: 1.0042x; 1.0042x over previous
#include <cuda_runtime.h>
#include <cuda_bf16.h>
#include <math.h>
#include <stdint.h>

#define BB 2
#define LL 4096
#define DD 1024
#define TOK (BB*LL)        // 8192
#define NH 16
#define HD 64
#define WIN 256
#define NE 8
#define FFH 4096
#define MAXTILE 136

// ---------------- scratch (static device memory, no runtime alloc) ----------
__device__ float g_xln[(size_t)TOK*DD];               // fp32 LN out (gate reads; LN3 only)
__device__ __nv_bfloat16 g_xh[(size_t)TOK*DD];        // split LN out
__device__ __nv_bfloat16 g_xl[(size_t)TOK*DD];
__device__ __nv_bfloat16 g_qkvh[(size_t)TOK*3*DD];    // split qkv (hi)
__device__ __nv_bfloat16 g_qkvl[(size_t)TOK*3*DD];    // split qkv (lo)
__device__ __nv_bfloat16 g_ah[(size_t)TOK*DD];        // split attention out
__device__ __nv_bfloat16 g_al[(size_t)TOK*DD];
__device__ float g_x[(size_t)TOK*DD];                 // running residual (fp32)
__device__ __nv_bfloat16 g_xrh[(size_t)TOK*DD];       // split post-MoE residual
__device__ __nv_bfloat16 g_xrl[(size_t)TOK*DD];
__device__ float g_moey[(size_t)NE*TOK*DD];
__device__ __nv_bfloat16 g_hh[(size_t)TOK*FFH];       // split FF hidden
__device__ __nv_bfloat16 g_hl[(size_t)TOK*FFH];
__device__ int2   g_topi[TOK];
__device__ float2 g_topw[TOK];
__device__ float  g_ent[TOK];

// sparse MoE routing state
__device__ int g_cnt[NE];
__device__ int g_idxflat[NE*TOK];
__device__ int g_pos[2*TOK];
__device__ int g_tile_rb[MAXTILE];
__device__ int g_tile_cnt[MAXTILE];
__device__ int g_tile_e[MAXTILE];
__device__ int g_ntiles;

// transposed + split bf16 weights  [N][K] layout
#define OFF_QKV  0u
#define OFF_ATT  3145728u
#define OFF_CONV 4194304u
#define OFF_EXP  7340032u
#define OFF_FF1  15728640u
#define OFF_FF2  19922944u
#define WT_TOTAL 24117248u
__device__ __nv_bfloat16 g_wh[WT_TOTAL];
__device__ __nv_bfloat16 g_wl[WT_TOTAL];

__device__ __forceinline__ float gelu_exact(float x) {
    return 0.5f * x * (1.0f + erff(x * 0.70710678118654752f));
}

__device__ __forceinline__ uint32_t smem_u32(const void* p) {
    uint32_t a;
    asm("{ .reg .u64 t; cvta.to.shared.u64 t, %1; cvt.u32.u64 %0, t; }" : "=r"(a) : "l"(p));
    return a;
}

__device__ __forceinline__ void ldm_x4(uint32_t* r, uint32_t addr) {
    asm volatile("ldmatrix.sync.aligned.m8n8.x4.shared.b16 {%0,%1,%2,%3}, [%4];"
                 : "=r"(r[0]), "=r"(r[1]), "=r"(r[2]), "=r"(r[3]) : "r"(addr));
}

__device__ __forceinline__ void ldm_x4_t(uint32_t* r, uint32_t addr) {
    asm volatile("ldmatrix.sync.aligned.m8n8.x4.trans.shared.b16 {%0,%1,%2,%3}, [%4];"
                 : "=r"(r[0]), "=r"(r[1]), "=r"(r[2]), "=r"(r[3]) : "r"(addr));
}

__device__ __forceinline__ void mma_bf16(float* d, const uint32_t* a, const uint32_t* b) {
    asm volatile(
        "mma.sync.aligned.m16n8k16.row.col.f32.bf16.bf16.f32 "
        "{%0,%1,%2,%3}, {%4,%5,%6,%7}, {%8,%9}, {%0,%1,%2,%3};"
        : "+f"(d[0]), "+f"(d[1]), "+f"(d[2]), "+f"(d[3])
        : "r"(a[0]), "r"(a[1]), "r"(a[2]), "r"(a[3]), "r"(b[0]), "r"(b[1]));
}

#define CP16(dst, src) \
    asm volatile("cp.async.cg.shared.global [%0], [%1], 16;" :: "r"(dst), "l"(src))
#define CP16Z(dst, src, sz) \
    asm volatile("cp.async.cg.shared.global [%0], [%1], 16, %2;" :: "r"(dst), "l"(src), "r"(sz))
#define CP_COMMIT() asm volatile("cp.async.commit_group;" ::: "memory")
#define CP_WAIT(n)  asm volatile("cp.async.wait_group %0;" :: "n"(n) : "memory")

__device__ __forceinline__ void split2(float a, float b, uint32_t& hi, uint32_t& lo) {
    __nv_bfloat16 ha = __float2bfloat16_rn(a), hb = __float2bfloat16_rn(b);
    float ra = a - __bfloat162float(ha), rb = b - __bfloat162float(hb);
    __nv_bfloat16 la = __float2bfloat16_rn(ra), lb = __float2bfloat16_rn(rb);
    hi = (uint32_t)__bfloat16_as_ushort(ha) | ((uint32_t)__bfloat16_as_ushort(hb) << 16);
    lo = (uint32_t)__bfloat16_as_ushort(la) | ((uint32_t)__bfloat16_as_ushort(lb) << 16);
}

// ---------------- shared GEMM machinery (R9 proven config) -----------------------
// 128x128 tile, 8 warps (2x4), warp tile 64x32, K-chunk 32, 2-stage, 2 CTA/SM.
#define ROWB   80
#define ASZ    10240          // 128 * 80
#define STAGE  40960          // A_h + A_l + B_h + B_l
#define GEMM_SMEM (2 * STAGE) // 81920

struct GemmCtx {
    uint32_t sb, foff, aoff, boff;
    int lane, wm, wn, frow, fhalf;
};

__device__ __forceinline__ void gemm_setup(GemmCtx& g, char* sm) {
    const int tid = threadIdx.x;
    g.sb = smem_u32(sm);
    g.lane = tid & 31;
    const int wid = tid >> 5;
    g.wm = wid >> 2; g.wn = wid & 3;
    g.frow = tid >> 1; g.fhalf = tid & 1;
    g.foff = (uint32_t)(g.frow * ROWB + g.fhalf * 32);
    g.aoff = (uint32_t)((g.wm * 64 + (g.lane & 15)) * ROWB + (g.lane >> 4) * 16);
    const int bgroup = g.lane >> 3, bwithin = g.lane & 7;
    g.boff = (uint32_t)((g.wn * 32 + (bgroup >> 1) * 8 + bwithin) * ROWB + (bgroup & 1) * 16);
}

__device__ __forceinline__ void cp_pair(uint32_t dst_h, uint32_t dst_l,
                                        const __nv_bfloat16* src_h,
                                        const __nv_bfloat16* src_l) {
    CP16(dst_h,      (const char*)src_h);
    CP16(dst_h + 16, (const char*)src_h + 16);
    CP16(dst_l,      (const char*)src_l);
    CP16(dst_l + 16, (const char*)src_l + 16);
}

__device__ __forceinline__ void compute_stage(const GemmCtx& g, int buf,
                                              float acc[4][4][4]) {
    const uint32_t sA_h = g.sb + buf * STAGE;
    const uint32_t sA_l = sA_h + ASZ;
    const uint32_t sB_h = sA_h + 2 * ASZ;
    const uint32_t sB_l = sA_h + 3 * ASZ;
    #pragma unroll
    for (int ks = 0; ks < 2; ks++) {
        uint32_t Ah[4][4], Al[4][4], Bhf[4][2], Blf[4][2];
        #pragma unroll
        for (int mt = 0; mt < 4; mt++) {
            ldm_x4(Ah[mt], sA_h + g.aoff + mt * (16 * ROWB) + ks * 32);
            ldm_x4(Al[mt], sA_l + g.aoff + mt * (16 * ROWB) + ks * 32);
        }
        #pragma unroll
        for (int n2 = 0; n2 < 2; n2++) {
            uint32_t r[4];
            ldm_x4(r, sB_h + g.boff + n2 * (16 * ROWB) + ks * 32);
            Bhf[n2*2][0] = r[0]; Bhf[n2*2][1] = r[1];
            Bhf[n2*2+1][0] = r[2]; Bhf[n2*2+1][1] = r[3];
            ldm_x4(r, sB_l + g.boff + n2 * (16 * ROWB) + ks * 32);
            Blf[n2*2][0] = r[0]; Blf[n2*2][1] = r[1];
            Blf[n2*2+1][0] = r[2]; Blf[n2*2+1][1] = r[3];
        }
        #pragma unroll
        for (int mt = 0; mt < 4; mt++)
            #pragma unroll
            for (int nt = 0; nt < 4; nt++) {
                mma_bf16(acc[mt][nt], Ah[mt], Bhf[nt]);
                mma_bf16(acc[mt][nt], Ah[mt], Blf[nt]);
                mma_bf16(acc[mt][nt], Al[mt], Bhf[nt]);
            }
    }
}

// ---------------- standard GEMM ---------------------------------------------------
template<bool GELU, bool RESID, bool OSPLIT>
__global__ void __launch_bounds__(256, 2) gemm_mma(const __nv_bfloat16* __restrict__ Ah,
                                                   const __nv_bfloat16* __restrict__ Al,
                                                   const __nv_bfloat16* __restrict__ Bh,
                                                   const __nv_bfloat16* __restrict__ Bl,
                                                   const float* __restrict__ bias,
                                                   const float* __restrict__ R,
                                                   float* __restrict__ C,
                                                   __nv_bfloat16* __restrict__ Oh,
                                                   __nv_bfloat16* __restrict__ Ol,
                                                   int M, int N, int K) {
    extern __shared__ char sm[];
    GemmCtx g; gemm_setup(g, sm);
    const int bm = blockIdx.y * 128, bn = blockIdx.x * 128;

    const __nv_bfloat16* Ahp = Ah + (size_t)(bm + g.frow) * K + g.fhalf * 16;
    const __nv_bfloat16* Alp = Al + (size_t)(bm + g.frow) * K + g.fhalf * 16;
    const __nv_bfloat16* Bhp = Bh + (size_t)(bn + g.frow) * K + g.fhalf * 16;
    const __nv_bfloat16* Blp = Bl + (size_t)(bn + g.frow) * K + g.fhalf * 16;

    float acc[4][4][4] = {};
    const int nst = K >> 5;

    auto issue = [&](int s, int buf) {
        const int k0 = s << 5;
        const uint32_t base = g.sb + buf * STAGE;
        cp_pair(base + g.foff,         base + ASZ + g.foff,   Ahp + k0, Alp + k0);
        cp_pair(base + 2*ASZ + g.foff, base + 3*ASZ + g.foff, Bhp + k0, Blp + k0);
        CP_COMMIT();
    };

    issue(0, 0);
    for (int s = 0; s < nst; s++) {
        const int buf = s & 1;
        if (s + 1 < nst) { issue(s + 1, buf ^ 1); CP_WAIT(1); }
        else             { CP_WAIT(0); }
        __syncthreads();
        compute_stage(g, buf, acc);
        __syncthreads();
    }

    const int r0base = bm + g.wm * 64 + (g.lane >> 2);
    const int cbase = bn + g.wn * 32 + (g.lane & 3) * 2;
    #pragma unroll
    for (int mt = 0; mt < 4; mt++) {
        #pragma unroll
        for (int nt = 0; nt < 4; nt++) {
            const int c = cbase + nt * 8;
            const float2 bb = *(const float2*)(bias + c);
            const int r0 = r0base + mt * 16;
            const int r1 = r0 + 8;
            float2 v0, v1;
            v0.x = acc[mt][nt][0] + bb.x; v0.y = acc[mt][nt][1] + bb.y;
            v1.x = acc[mt][nt][2] + bb.x; v1.y = acc[mt][nt][3] + bb.y;
            if (GELU) {
                v0.x = gelu_exact(v0.x); v0.y = gelu_exact(v0.y);
                v1.x = gelu_exact(v1.x); v1.y = gelu_exact(v1.y);
            }
            if (RESID) {
                const float2 q0 = *(const float2*)(R + (size_t)r0 * N + c);
                const float2 q1 = *(const float2*)(R + (size_t)r1 * N + c);
                v0.x += q0.x; v0.y += q0.y; v1.x += q1.x; v1.y += q1.y;
            }
            if (OSPLIT) {
                uint32_t h0, l0, h1, l1;
                split2(v0.x, v0.y, h0, l0);
                split2(v1.x, v1.y, h1, l1);
                *(uint32_t*)(Oh + (size_t)r0 * N + c) = h0;
                *(uint32_t*)(Ol + (size_t)r0 * N + c) = l0;
                *(uint32_t*)(Oh + (size_t)r1 * N + c) = h1;
                *(uint32_t*)(Ol + (size_t)r1 * N + c) = l1;
            } else {
                *(float2*)(C + (size_t)r0 * N + c) = v0;
                *(float2*)(C + (size_t)r1 * N + c) = v1;
            }
        }
    }
}

// ---------------- conv GEMM with fused dilated im2col gather -------------------
__global__ void __launch_bounds__(256, 2) gemm_conv(const __nv_bfloat16* __restrict__ xh,
                                                    const __nv_bfloat16* __restrict__ xl,
                                                    const __nv_bfloat16* __restrict__ Bh,
                                                    const __nv_bfloat16* __restrict__ Bl,
                                                    const float* __restrict__ bias,
                                                    float* __restrict__ C) {
    extern __shared__ char sm[];
    GemmCtx g; gemm_setup(g, sm);
    const int bm = blockIdx.y * 128, bn = blockIdx.x * 128;
    const int N = DD, K = 3 * DD;

    const int t = bm + g.frow;
    const int b = t >> 12, l = t & (LL - 1);
    const __nv_bfloat16* Bhp = Bh + (size_t)(bn + g.frow) * K + g.fhalf * 16;
    const __nv_bfloat16* Blp = Bl + (size_t)(bn + g.frow) * K + g.fhalf * 16;

    float acc[4][4][4] = {};
    const int nst = K >> 5;  // 96

    auto issue = [&](int s, int buf) {
        const int k0 = s << 5;
        const uint32_t base = g.sb + buf * STAGE;
        const int kk = k0 + g.fhalf * 16;
        const int tap = kk >> 10, din = kk & 1023;
        const int ls = l + 2 * tap - 2;
        const int ok = ((unsigned)ls < (unsigned)LL) ? 16 : 0;
        const int lsc = min(max(ls, 0), LL - 1);
        const size_t abase = ((size_t)(b * LL + lsc)) * DD + din;
        const char* sah = (const char*)(xh + abase);
        const char* sal = (const char*)(xl + abase);
        CP16Z(base + g.foff,            sah,      ok);
        CP16Z(base + g.foff + 16,       sah + 16, ok);
        CP16Z(base + ASZ + g.foff,      sal,      ok);
        CP16Z(base + ASZ + g.foff + 16, sal + 16, ok);
        cp_pair(base + 2*ASZ + g.foff, base + 3*ASZ + g.foff, Bhp + k0, Blp + k0);
        CP_COMMIT();
    };

    issue(0, 0);
    for (int s = 0; s < nst; s++) {
        const int buf = s & 1;
        if (s + 1 < nst) { issue(s + 1, buf ^ 1); CP_WAIT(1); }
        else             { CP_WAIT(0); }
        __syncthreads();
        compute_stage(g, buf, acc);
        __syncthreads();
    }

    const int r0base = bm + g.wm * 64 + (g.lane >> 2);
    const int cbase = bn + g.wn * 32 + (g.lane & 3) * 2;
    #pragma unroll
    for (int mt = 0; mt < 4; mt++) {
        #pragma unroll
        for (int nt = 0; nt < 4; nt++) {
            const int c = cbase + nt * 8;
            const float2 bb = *(const float2*)(bias + c);
            const int r0 = r0base + mt * 16;
            const int r1 = r0 + 8;
            const float2 q0 = *(const float2*)(C + (size_t)r0 * N + c);
            const float2 q1 = *(const float2*)(C + (size_t)r1 * N + c);
            float2 v0, v1;
            v0.x = acc[mt][nt][0] + bb.x + q0.x; v0.y = acc[mt][nt][1] + bb.y + q0.y;
            v1.x = acc[mt][nt][2] + bb.x + q1.x; v1.y = acc[mt][nt][3] + bb.y + q1.y;
            *(float2*)(C + (size_t)r0 * N + c) = v0;
            *(float2*)(C + (size_t)r1 * N + c) = v1;
        }
    }
}

// ---------------- sparse MoE grouped GEMM ---------------------------------------
__global__ void __launch_bounds__(256, 2) gemm_moe(const __nv_bfloat16* __restrict__ xh,
                                                   const __nv_bfloat16* __restrict__ xl,
                                                   const __nv_bfloat16* __restrict__ WhBase,
                                                   const __nv_bfloat16* __restrict__ WlBase,
                                                   const float* __restrict__ ebias,
                                                   float* __restrict__ Y) {
    if ((int)blockIdx.y >= g_ntiles) return;
    extern __shared__ char sm[];
    GemmCtx g; gemm_setup(g, sm);
    const int rb = g_tile_rb[blockIdx.y];
    const int tcnt = g_tile_cnt[blockIdx.y];
    const int e = g_tile_e[blockIdx.y];
    const int bn = blockIdx.x * 128;
    const int N = DD, K = DD;

    const int tok = g_idxflat[rb + g.frow];
    const __nv_bfloat16* Ahp = xh + (size_t)tok * K + g.fhalf * 16;
    const __nv_bfloat16* Alp = xl + (size_t)tok * K + g.fhalf * 16;
    const __nv_bfloat16* Bhp = WhBase + (size_t)e * DD * DD + (size_t)(bn + g.frow) * K + g.fhalf * 16;
    const __nv_bfloat16* Blp = WlBase + (size_t)e * DD * DD + (size_t)(bn + g.frow) * K + g.fhalf * 16;
    const float* bias = ebias + (size_t)e * DD;

    float acc[4][4][4] = {};
    const int nst = K >> 5;

    auto issue = [&](int s, int buf) {
        const int k0 = s << 5;
        const uint32_t base = g.sb + buf * STAGE;
        cp_pair(base + g.foff,         base + ASZ + g.foff,   Ahp + k0, Alp + k0);
        cp_pair(base + 2*ASZ + g.foff, base + 3*ASZ + g.foff, Bhp + k0, Blp + k0);
        CP_COMMIT();
    };

    issue(0, 0);
    for (int s = 0; s < nst; s++) {
        const int buf = s & 1;
        if (s + 1 < nst) { issue(s + 1, buf ^ 1); CP_WAIT(1); }
        else             { CP_WAIT(0); }
        __syncthreads();
        compute_stage(g, buf, acc);
        __syncthreads();
    }

    const int lrbase = g.wm * 64 + (g.lane >> 2);
    const int cbase = bn + g.wn * 32 + (g.lane & 3) * 2;
    #pragma unroll
    for (int mt = 0; mt < 4; mt++) {
        #pragma unroll
        for (int nt = 0; nt < 4; nt++) {
            const int c = cbase + nt * 8;
            const float2 bb = *(const float2*)(bias + c);
            const int lr0 = lrbase + mt * 16;
            const int lr1 = lr0 + 8;
            float2 v0, v1;
            v0.x = gelu_exact(acc[mt][nt][0] + bb.x);
            v0.y = gelu_exact(acc[mt][nt][1] + bb.y);
            v1.x = gelu_exact(acc[mt][nt][2] + bb.x);
            v1.y = gelu_exact(acc[mt][nt][3] + bb.y);
            if (lr0 < tcnt) *(float2*)(Y + (size_t)(rb + lr0) * N + c) = v0;
            if (lr1 < tcnt) *(float2*)(Y + (size_t)(rb + lr1) * N + c) = v1;
        }
    }
}

// ---------------- tensor-core windowed flash attention --------------------------
#define AROWB 144
__global__ void __launch_bounds__(256) attn_tc(const __nv_bfloat16* __restrict__ qh,
                                               const __nv_bfloat16* __restrict__ ql,
                                               __nv_bfloat16* __restrict__ oh,
                                               __nv_bfloat16* __restrict__ ol) {
    __shared__ char smn[4 * 32 * AROWB];   // Kh, Kl, Vh, Vl (32 x 144B each)
    const int h = blockIdx.x & 15;
    const int w = (blockIdx.x >> 4) & 15;
    const int b = blockIdx.x >> 8;
    const int t0 = b * LL + w * WIN;
    const int tid = threadIdx.x, lane = tid & 31, wid = tid >> 5;
    const int gid = lane >> 2, tig = lane & 3;
    const uint32_t sb = smem_u32(smn);
    const uint32_t sKh = sb, sKl = sb + 4608, sVh = sb + 9216, sVl = sb + 13824;

    uint32_t Qh[2][4][4], Ql[2][4][4];
    #pragma unroll
    for (int mt = 0; mt < 2; mt++) {
        const int r0 = t0 + wid * 32 + mt * 16 + gid;
        const size_t q0 = (size_t)r0 * 3072 + h * 64;
        const size_t q1 = q0 + (size_t)8 * 3072;
        #pragma unroll
        for (int kk = 0; kk < 4; kk++) {
            const int c = kk * 16 + 2 * tig;
            Qh[mt][kk][0] = *(const uint32_t*)(qh + q0 + c);
            Ql[mt][kk][0] = *(const uint32_t*)(ql + q0 + c);
            Qh[mt][kk][1] = *(const uint32_t*)(qh + q1 + c);
            Ql[mt][kk][1] = *(const uint32_t*)(ql + q1 + c);
            Qh[mt][kk][2] = *(const uint32_t*)(qh + q0 + c + 8);
            Ql[mt][kk][2] = *(const uint32_t*)(ql + q0 + c + 8);
            Qh[mt][kk][3] = *(const uint32_t*)(qh + q1 + c + 8);
            Ql[mt][kk][3] = *(const uint32_t*)(ql + q1 + c + 8);
        }
    }

    float o[2][8][4] = {};
    float mrun[2][2] = {{-1e30f, -1e30f}, {-1e30f, -1e30f}};
    float lrun[2][2] = {};

    const int stok = tid >> 3, sq = tid & 7;
    const size_t kvoff = (size_t)(t0 + stok) * 3072 + 1024 + h * 64 + sq * 8;
    const uint32_t soff = (uint32_t)(stok * AROWB + sq * 16);

    const uint32_t kaddr = (uint32_t)((((lane >> 4) & 1) * 8 + (lane & 7)) * AROWB
                                      + ((lane >> 3) & 1) * 16);

    for (int c8 = 0; c8 < 8; c8++) {
        __syncthreads();
        {
            const size_t kbase = kvoff + (size_t)(c8 * 32) * 3072;
            *(uint4*)(smn + soff)         = *(const uint4*)(qh + kbase);
            *(uint4*)(smn + 4608 + soff)  = *(const uint4*)(ql + kbase);
            *(uint4*)(smn + 9216 + soff)  = *(const uint4*)(qh + kbase + 1024);
            *(uint4*)(smn + 13824 + soff) = *(const uint4*)(ql + kbase + 1024);
        }
        __syncthreads();

        float s[2][4][4] = {};
        #pragma unroll
        for (int kk = 0; kk < 4; kk++) {
            #pragma unroll
            for (int n2 = 0; n2 < 2; n2++) {
                uint32_t rbh[4], rbl[4];
                const uint32_t a = kaddr + (uint32_t)(n2 * 16 * AROWB + kk * 32);
                ldm_x4(rbh, sKh + a);
                ldm_x4(rbl, sKl + a);
                #pragma unroll
                for (int mt = 0; mt < 2; mt++) {
                    mma_bf16(s[mt][n2*2],   Qh[mt][kk], rbh);
                    mma_bf16(s[mt][n2*2],   Qh[mt][kk], rbl);
                    mma_bf16(s[mt][n2*2],   Ql[mt][kk], rbh);
                    mma_bf16(s[mt][n2*2+1], Qh[mt][kk], rbh + 2);
                    mma_bf16(s[mt][n2*2+1], Qh[mt][kk], rbl + 2);
                    mma_bf16(s[mt][n2*2+1], Ql[mt][kk], rbh + 2);
                }
            }
        }

        uint32_t Ph[2][2][4], Pl[2][2][4];
        #pragma unroll
        for (int mt = 0; mt < 2; mt++) {
            float m0 = -1e30f, m1 = -1e30f;
            #pragma unroll
            for (int nt = 0; nt < 4; nt++) {
                #pragma unroll
                for (int i = 0; i < 4; i++) s[mt][nt][i] *= 0.125f;
                m0 = fmaxf(m0, fmaxf(s[mt][nt][0], s[mt][nt][1]));
                m1 = fmaxf(m1, fmaxf(s[mt][nt][2], s[mt][nt][3]));
            }
            m0 = fmaxf(m0, __shfl_xor_sync(0xffffffffu, m0, 1));
            m0 = fmaxf(m0, __shfl_xor_sync(0xffffffffu, m0, 2));
            m1 = fmaxf(m1, __shfl_xor_sync(0xffffffffu, m1, 1));
            m1 = fmaxf(m1, __shfl_xor_sync(0xffffffffu, m1, 2));
            const float mn0 = fmaxf(mrun[mt][0], m0);
            const float mn1 = fmaxf(mrun[mt][1], m1);
            const float f0 = __expf(mrun[mt][0] - mn0);
            const float f1 = __expf(mrun[mt][1] - mn1);
            mrun[mt][0] = mn0; mrun[mt][1] = mn1;
            float l0 = 0.f, l1 = 0.f;
            #pragma unroll
            for (int nt = 0; nt < 4; nt++) {
                s[mt][nt][0] = __expf(s[mt][nt][0] - mn0);
                s[mt][nt][1] = __expf(s[mt][nt][1] - mn0);
                s[mt][nt][2] = __expf(s[mt][nt][2] - mn1);
                s[mt][nt][3] = __expf(s[mt][nt][3] - mn1);
                l0 += s[mt][nt][0] + s[mt][nt][1];
                l1 += s[mt][nt][2] + s[mt][nt][3];
            }
            l0 += __shfl_xor_sync(0xffffffffu, l0, 1);
            l0 += __shfl_xor_sync(0xffffffffu, l0, 2);
            l1 += __shfl_xor_sync(0xffffffffu, l1, 1);
            l1 += __shfl_xor_sync(0xffffffffu, l1, 2);
            lrun[mt][0] = lrun[mt][0] * f0 + l0;
            lrun[mt][1] = lrun[mt][1] * f1 + l1;
            #pragma unroll
            for (int nt = 0; nt < 8; nt++) {
                o[mt][nt][0] *= f0; o[mt][nt][1] *= f0;
                o[mt][nt][2] *= f1; o[mt][nt][3] *= f1;
            }
            #pragma unroll
            for (int kk2 = 0; kk2 < 2; kk2++) {
                split2(s[mt][2*kk2][0],   s[mt][2*kk2][1],   Ph[mt][kk2][0], Pl[mt][kk2][0]);
                split2(s[mt][2*kk2][2],   s[mt][2*kk2][3],   Ph[mt][kk2][1], Pl[mt][kk2][1]);
                split2(s[mt][2*kk2+1][0], s[mt][2*kk2+1][1], Ph[mt][kk2][2], Pl[mt][kk2][2]);
                split2(s[mt][2*kk2+1][2], s[mt][2*kk2+1][3], Ph[mt][kk2][3], Pl[mt][kk2][3]);
            }
        }

        #pragma unroll
        for (int dp = 0; dp < 4; dp++) {
            #pragma unroll
            for (int kk2 = 0; kk2 < 2; kk2++) {
                uint32_t vbh[4], vbl[4];
                const uint32_t va = (uint32_t)((kk2 * 16 + (lane & 7) + ((lane >> 3) & 1) * 8) * AROWB
                                               + (dp * 2 + ((lane >> 4) & 1)) * 16);
                ldm_x4_t(vbh, sVh + va);
                ldm_x4_t(vbl, sVl + va);
                #pragma unroll
                for (int mt = 0; mt < 2; mt++) {
                    mma_bf16(o[mt][dp*2],   Ph[mt][kk2], vbh);
                    mma_bf16(o[mt][dp*2],   Ph[mt][kk2], vbl);
                    mma_bf16(o[mt][dp*2],   Pl[mt][kk2], vbh);
                    mma_bf16(o[mt][dp*2+1], Ph[mt][kk2], vbh + 2);
                    mma_bf16(o[mt][dp*2+1], Ph[mt][kk2], vbl + 2);
                    mma_bf16(o[mt][dp*2+1], Pl[mt][kk2], vbh + 2);
                }
            }
        }
    }

    #pragma unroll
    for (int mt = 0; mt < 2; mt++) {
        const float i0 = 1.f / lrun[mt][0], i1 = 1.f / lrun[mt][1];
        const int r0 = t0 + wid * 32 + mt * 16 + gid;
        #pragma unroll
        for (int nt = 0; nt < 8; nt++) {
            const int c = h * 64 + nt * 8 + 2 * tig;
            uint32_t ph, pl;
            split2(o[mt][nt][0] * i0, o[mt][nt][1] * i0, ph, pl);
            *(uint32_t*)(oh + (size_t)r0 * 1024 + c) = ph;
            *(uint32_t*)(ol + (size_t)r0 * 1024 + c) = pl;
            split2(o[mt][nt][2] * i1, o[mt][nt][3] * i1, ph, pl);
            *(uint32_t*)(oh + (size_t)(r0 + 8) * 1024 + c) = ph;
            *(uint32_t*)(ol + (size_t)(r0 + 8) * 1024 + c) = pl;
        }
    }
}

// ---------------- weight transpose + bf16 split ---------------------------------
__global__ void __launch_bounds__(256) wt_kernel(const float* __restrict__ W,
                                                 __nv_bfloat16* __restrict__ Th,
                                                 __nv_bfloat16* __restrict__ Tl,
                                                 int K, int N) {
    __shared__ float tile[32][33];
    const size_t slab = (size_t)blockIdx.z * K * N;
    const int k0 = blockIdx.y * 32, n0 = blockIdx.x * 32;
    const int x = threadIdx.x, y = threadIdx.y;
    #pragma unroll
    for (int j = 0; j < 32; j += 8)
        tile[y + j][x] = W[slab + (size_t)(k0 + y + j) * N + n0 + x];
    __syncthreads();
    #pragma unroll
    for (int j = 0; j < 32; j += 8) {
        const float v = tile[x][y + j];
        const int n = n0 + y + j, k = k0 + x;
        const __nv_bfloat16 h = __float2bfloat16_rn(v);
        Th[slab + (size_t)n * K + k] = h;
        Tl[slab + (size_t)n * K + k] = __float2bfloat16_rn(v - __bfloat162float(h));
    }
}

__global__ void __launch_bounds__(256) convw_t(const float* __restrict__ cw,
                                               __nv_bfloat16* __restrict__ Th,
                                               __nv_bfloat16* __restrict__ Tl) {
    const size_t idx = (size_t)blockIdx.x * 256 + threadIdx.x;
    const int dout = (int)(idx / 3072);
    const int r = (int)(idx % 3072);
    const int tap = r >> 10, din = r & 1023;
    const float v = cw[((size_t)dout * DD + din) * 3 + tap];
    const __nv_bfloat16 h = __float2bfloat16_rn(v);
    Th[idx] = h;
    Tl[idx] = __float2bfloat16_rn(v - __bfloat162float(h));
}

// ---------------- LayerNorm (optional fp32 + split bf16 outputs) -----------------
__global__ void __launch_bounds__(256) ln_kernel(const float* __restrict__ x,
                                                 const float* __restrict__ g,
                                                 const float* __restrict__ b,
                                                 float* __restrict__ y,
                                                 __nv_bfloat16* __restrict__ yh,
                                                 __nv_bfloat16* __restrict__ yl) {
    __shared__ float red[8];
    __shared__ float sh_mu, sh_inv;
    const int tid = threadIdx.x, lane = tid & 31, warp = tid >> 5;
    const float4 xv = ((const float4*)(x + (size_t)blockIdx.x * DD))[tid];

    float s = xv.x + xv.y + xv.z + xv.w;
    #pragma unroll
    for (int o = 16; o > 0; o >>= 1) s += __shfl_down_sync(0xffffffffu, s, o);
    if (lane == 0) red[warp] = s;
    __syncthreads();
    if (tid == 0) {
        float t = 0.f;
        #pragma unroll
        for (int i = 0; i < 8; i++) t += red[i];
        sh_mu = t * (1.0f / DD);
    }
    __syncthreads();
    const float mu = sh_mu;
    const float dx = xv.x - mu, dy = xv.y - mu, dz = xv.z - mu, dw = xv.w - mu;
    float s2 = dx*dx + dy*dy + dz*dz + dw*dw;
    #pragma unroll
    for (int o = 16; o > 0; o >>= 1) s2 += __shfl_down_sync(0xffffffffu, s2, o);
    if (lane == 0) red[warp] = s2;
    __syncthreads();
    if (tid == 0) {
        float t = 0.f;
        #pragma unroll
        for (int i = 0; i < 8; i++) t += red[i];
        sh_inv = rsqrtf(t * (1.0f / DD) + 1e-5f);
    }
    __syncthreads();
    const float inv = sh_inv;
    const float4 gv = ((const float4*)g)[tid];
    const float4 bv = ((const float4*)b)[tid];
    float4 o;
    o.x = dx * inv * gv.x + bv.x;
    o.y = dy * inv * gv.y + bv.y;
    o.z = dz * inv * gv.z + bv.z;
    o.w = dw * inv * gv.w + bv.w;
    const size_t idx = (size_t)blockIdx.x * DD + tid * 4;
    if (y) *(float4*)(y + idx) = o;
    uint32_t h0, l0, h1, l1;
    split2(o.x, o.y, h0, l0);
    split2(o.z, o.w, h1, l1);
    *(uint32_t*)(yh + idx)     = h0;
    *(uint32_t*)(yh + idx + 2) = h1;
    *(uint32_t*)(yl + idx)     = l0;
    *(uint32_t*)(yl + idx + 2) = l1;
}

// ---------------- gate: softmax, entropy, top-2 ---------------------------------
__global__ void __launch_bounds__(256) gate_kernel(const float* __restrict__ xln,
                                                   const float* __restrict__ gw,
                                                   const float* __restrict__ gb) {
    if (blockIdx.x == 0 && threadIdx.x < NE) g_cnt[threadIdx.x] = 0;
    const int warp = threadIdx.x >> 5, lane = threadIdx.x & 31;
    const int t = blockIdx.x * 8 + warp;
    const float* xr = xln + (size_t)t * DD;

    float a[8] = {0.f,0.f,0.f,0.f,0.f,0.f,0.f,0.f};
    for (int i = lane; i < DD; i += 32) {
        const float xv = xr[i];
        const float* g8 = gw + i * 8;
        #pragma unroll
        for (int e = 0; e < 8; e++) a[e] += xv * g8[e];
    }
    #pragma unroll
    for (int e = 0; e < 8; e++) {
        #pragma unroll
        for (int o = 16; o > 0; o >>= 1) a[e] += __shfl_down_sync(0xffffffffu, a[e], o);
    }
    if (lane == 0) {
        float lg[8], mx = -1e30f;
        #pragma unroll
        for (int e = 0; e < 8; e++) { lg[e] = a[e] + gb[e]; mx = fmaxf(mx, lg[e]); }
        float p[8], den = 0.f;
        #pragma unroll
        for (int e = 0; e < 8; e++) { p[e] = expf(lg[e] - mx); den += p[e]; }
        float ent = 0.f;
        #pragma unroll
        for (int e = 0; e < 8; e++) { p[e] /= den; ent -= p[e] * logf(p[e] + 1e-10f); }
        g_ent[t] = ent;

        int i0 = 0; float v0 = p[0];
        #pragma unroll
        for (int e = 1; e < 8; e++) if (p[e] > v0) { v0 = p[e]; i0 = e; }
        int i1 = -1; float v1 = -1e30f;
        #pragma unroll
        for (int e = 0; e < 8; e++) if (e != i0 && p[e] > v1) { v1 = p[e]; i1 = e; }
        const float sw = v0 + v1;
        g_topi[t] = make_int2(i0, i1);
        g_topw[t] = make_float2(v0 / sw, v1 / sw);
    }
}

// ---------------- routing kernels -------------------------------------------------
__global__ void __launch_bounds__(256) scatter_kernel() {
    const int t = blockIdx.x * 256 + threadIdx.x;
    if (t >= TOK) return;
    const int2 ii = g_topi[t];
    const int p0 = atomicAdd(&g_cnt[ii.x], 1);
    g_idxflat[ii.x * TOK + p0] = t;
    g_pos[2 * t] = ii.x * TOK + p0;
    const int p1 = atomicAdd(&g_cnt[ii.y], 1);
    g_idxflat[ii.y * TOK + p1] = t;
    g_pos[2 * t + 1] = ii.y * TOK + p1;
}

__global__ void __launch_bounds__(256) tile_build() {
    __shared__ int scnt[NE];
    if (threadIdx.x < NE) scnt[threadIdx.x] = g_cnt[threadIdx.x];
    __syncthreads();
    if (threadIdx.x == 0) {
        int nt = 0;
        for (int e = 0; e < NE; e++) {
            const int c = scnt[e];
            const int t = (c + 127) >> 7;
            for (int i = 0; i < t; i++) {
                g_tile_rb[nt] = e * TOK + i * 128;
                g_tile_cnt[nt] = min(128, c - i * 128);
                g_tile_e[nt] = e;
                nt++;
            }
        }
        g_ntiles = nt;
    }
    for (int j = threadIdx.x; j < NE * 128; j += 256) {
        const int e = j >> 7;
        const int c = scnt[e];
        const int off = c + (j & 127);
        const int lim = ((c + 127) >> 7) << 7;
        if (off < lim) g_idxflat[e * TOK + off] = 0;
    }
}

// ---------------- MoE combine: update fp32 resid + emit split ------------------
__global__ void __launch_bounds__(256) combine_kernel(const float* __restrict__ Y,
                                                      float* __restrict__ x,
                                                      __nv_bfloat16* __restrict__ xh,
                                                      __nv_bfloat16* __restrict__ xl) {
    const int t = blockIdx.x;
    const int d = threadIdx.x * 4;
    const int p0 = g_pos[2 * t], p1 = g_pos[2 * t + 1];
    const float2 ww = g_topw[t];
    const float4 a = *(const float4*)(Y + (size_t)p0 * DD + d);
    const float4 b = *(const float4*)(Y + (size_t)p1 * DD + d);
    const size_t idx = (size_t)t * DD + d;
    float4 xv = *(float4*)(x + idx);
    xv.x += ww.x * a.x + ww.y * b.x;
    xv.y += ww.x * a.y + ww.y * b.y;
    xv.z += ww.x * a.z + ww.y * b.z;
    xv.w += ww.x * a.w + ww.y * b.w;
    *(float4*)(x + idx) = xv;
    uint32_t h0, l0, h1, l1;
    split2(xv.x, xv.y, h0, l0);
    split2(xv.z, xv.w, h1, l1);
    *(uint32_t*)(xh + idx)     = h0;
    *(uint32_t*)(xh + idx + 2) = h1;
    *(uint32_t*)(xl + idx)     = l0;
    *(uint32_t*)(xl + idx + 2) = l1;
}

// ---------------- deterministic entropy reduction -------------------------------
__global__ void __launch_bounds__(256) ent_reduce(float* __restrict__ out) {
    __shared__ float sm[256];
    float s = 0.f;
    for (int i = threadIdx.x; i < TOK; i += 256) s += g_ent[i];
    sm[threadIdx.x] = s;
    __syncthreads();
    #pragma unroll
    for (int o = 128; o > 0; o >>= 1) {
        if (threadIdx.x < o) sm[threadIdx.x] += sm[threadIdx.x + o];
        __syncthreads();
    }
    if (threadIdx.x == 0) out[0] = 0.1f * sm[0] / (float)TOK;
}

// ---------------- launch ----------------------------------------------------------
extern "C" void kernel_launch(void* const* d_in, const int* in_sizes, int n_in,
                              void* d_out, int out_size) {
    const float* x          = (const float*)d_in[0];
    const float* ln1_g      = (const float*)d_in[1];
    const float* ln1_b      = (const float*)d_in[2];
    const float* qkv_w      = (const float*)d_in[3];
    const float* qkv_b      = (const float*)d_in[4];
    const float* attn_out_w = (const float*)d_in[5];
    const float* attn_out_b = (const float*)d_in[6];
    const float* ln2_g      = (const float*)d_in[7];
    const float* ln2_b      = (const float*)d_in[8];
    const float* conv_w     = (const float*)d_in[9];
    const float* conv_b     = (const float*)d_in[10];
    const float* ln3_g      = (const float*)d_in[11];
    const float* ln3_b      = (const float*)d_in[12];
    const float* gate_w     = (const float*)d_in[13];
    const float* gate_b     = (const float*)d_in[14];
    const float* expert_w   = (const float*)d_in[15];
    const float* expert_b   = (const float*)d_in[16];
    const float* ff_w1      = (const float*)d_in[17];
    const float* ff_b1      = (const float*)d_in[18];
    const float* ff_w2      = (const float*)d_in[19];
    const float* ff_b2      = (const float*)d_in[20];
    float* out = (float*)d_out;

    float *xln, *xr, *moey;
    __nv_bfloat16 *wh, *wl, *xh, *xl, *qh, *ql, *ah, *al, *xrh, *xrl, *hh, *hl;
    cudaGetSymbolAddress((void**)&xln,  g_xln);
    cudaGetSymbolAddress((void**)&xr,   g_x);
    cudaGetSymbolAddress((void**)&moey, g_moey);
    cudaGetSymbolAddress((void**)&wh,   g_wh);
    cudaGetSymbolAddress((void**)&wl,   g_wl);
    cudaGetSymbolAddress((void**)&xh,   g_xh);
    cudaGetSymbolAddress((void**)&xl,   g_xl);
    cudaGetSymbolAddress((void**)&qh,   g_qkvh);
    cudaGetSymbolAddress((void**)&ql,   g_qkvl);
    cudaGetSymbolAddress((void**)&ah,   g_ah);
    cudaGetSymbolAddress((void**)&al,   g_al);
    cudaGetSymbolAddress((void**)&xrh,  g_xrh);
    cudaGetSymbolAddress((void**)&xrl,  g_xrl);
    cudaGetSymbolAddress((void**)&hh,   g_hh);
    cudaGetSymbolAddress((void**)&hl,   g_hl);

    cudaFuncSetAttribute(gemm_mma<false, false, true>,  cudaFuncAttributeMaxDynamicSharedMemorySize, GEMM_SMEM);
    cudaFuncSetAttribute(gemm_mma<false, true, false>,  cudaFuncAttributeMaxDynamicSharedMemorySize, GEMM_SMEM);
    cudaFuncSetAttribute(gemm_mma<true, false, true>,   cudaFuncAttributeMaxDynamicSharedMemorySize, GEMM_SMEM);
    cudaFuncSetAttribute(gemm_conv, cudaFuncAttributeMaxDynamicSharedMemorySize, GEMM_SMEM);
    cudaFuncSetAttribute(gemm_moe,  cudaFuncAttributeMaxDynamicSharedMemorySize, GEMM_SMEM);

    const dim3 tblk(32, 8);

    // side stream for weight prep (created per call; intentionally leaked —
    // kernel_launch runs only for correctness + capture)
    cudaStream_t sw;
    cudaEvent_t ev_fork, ev_qkvw, ev_wt;
    cudaStreamCreateWithFlags(&sw, cudaStreamNonBlocking);
    cudaEventCreateWithFlags(&ev_fork, cudaEventDisableTiming);
    cudaEventCreateWithFlags(&ev_qkvw, cudaEventDisableTiming);
    cudaEventCreateWithFlags(&ev_wt,   cudaEventDisableTiming);

    // main: LN1 (independent of weights)
    ln_kernel<<<TOK, 256>>>(x, ln1_g, ln1_b, nullptr, xh, xl);
    cudaEventRecord(ev_fork, 0);
    cudaStreamWaitEvent(sw, ev_fork, 0);

    // side stream: all weight transforms (qkv first — it's on the critical path)
    wt_kernel<<<dim3(3072/32, 1024/32), tblk, 0, sw>>>(qkv_w, wh + OFF_QKV, wl + OFF_QKV, 1024, 3072);
    cudaEventRecord(ev_qkvw, sw);
    wt_kernel<<<dim3(1024/32, 1024/32), tblk, 0, sw>>>(attn_out_w, wh + OFF_ATT, wl + OFF_ATT, 1024, 1024);
    convw_t<<<(1024*3072)/256, 256, 0, sw>>>(conv_w, wh + OFF_CONV, wl + OFF_CONV);
    wt_kernel<<<dim3(4096/32, 1024/32), tblk, 0, sw>>>(ff_w1, wh + OFF_FF1, wl + OFF_FF1, 1024, 4096);
    wt_kernel<<<dim3(1024/32, 1024/32, NE), tblk, 0, sw>>>(expert_w, wh + OFF_EXP, wl + OFF_EXP, 1024, 1024);
    wt_kernel<<<dim3(1024/32, 4096/32), tblk, 0, sw>>>(ff_w2, wh + OFF_FF2, wl + OFF_FF2, 4096, 1024);
    cudaEventRecord(ev_wt, sw);

    // main: qkv GEMM as soon as its weights land; attention overlaps the rest
    cudaStreamWaitEvent(0, ev_qkvw, 0);
    gemm_mma<false, false, true><<<dim3(3072/128, TOK/128), 256, GEMM_SMEM>>>(
        xh, xl, wh + OFF_QKV, wl + OFF_QKV, qkv_b, nullptr, nullptr, qh, ql,
        TOK, 3072, 1024);
    attn_tc<<<BB * (LL / WIN) * NH, 256>>>(qh, ql, ah, al);

    // join: all remaining weights must be ready before the proj GEMM
    cudaStreamWaitEvent(0, ev_wt, 0);
    gemm_mma<false, true, false><<<dim3(1024/128, TOK/128), 256, GEMM_SMEM>>>(
        ah, al, wh + OFF_ATT, wl + OFF_ATT, attn_out_b, x, xr, nullptr, nullptr,
        TOK, 1024, 1024);

    // 2) LN2 -> dilated conv GEMM (fused im2col gather, +resid in place)
    ln_kernel<<<TOK, 256>>>(xr, ln2_g, ln2_b, nullptr, xh, xl);
    gemm_conv<<<dim3(1024/128, TOK/128), 256, GEMM_SMEM>>>(
        xh, xl, wh + OFF_CONV, wl + OFF_CONV, conv_b, xr);

    // 3) LN3 -> gate -> sparse top-2 MoE -> combine (emits split resid)
    ln_kernel<<<TOK, 256>>>(xr, ln3_g, ln3_b, xln, xh, xl);
    gate_kernel<<<TOK / 8, 256>>>(xln, gate_w, gate_b);
    scatter_kernel<<<TOK / 256, 256>>>();
    tile_build<<<1, 256>>>();
    gemm_moe<<<dim3(1024/128, MAXTILE), 256, GEMM_SMEM>>>(
        xh, xl, wh + OFF_EXP, wl + OFF_EXP, expert_b, moey);
    combine_kernel<<<TOK, 256>>>(moey, xr, xrh, xrl);

    // 4) FF1 (gelu, split out) -> FF2 (+resid -> out), entropy scalar
    gemm_mma<true, false, true><<<dim3(FFH/128, TOK/128), 256, GEMM_SMEM>>>(
        xrh, xrl, wh + OFF_FF1, wl + OFF_FF1, ff_b1, nullptr, nullptr, hh, hl,
        TOK, FFH, 1024);
    gemm_mma<false, true, false><<<dim3(1024/128, TOK/128), 256, GEMM_SMEM>>>(
        hh, hl, wh + OFF_FF2, wl + OFF_FF2, ff_b2, xr, out, nullptr, nullptr,
        TOK, 1024, FFH);
    ent_reduce<<<1, 256>>>(out + (size_t)TOK * DD);
}

// round 17
// speedup vs baseline: 1.0424x; 1.0381x over previous
#include <cuda_runtime.h>
#include <cuda_bf16.h>
#include <math.h>
#include <stdint.h>

#define BB 2
#define LL 4096
#define DD 1024
#define TOK (BB*LL)        // 8192
#define NH 16
#define HD 64
#define WIN 256
#define NE 8
#define FFH 4096
#define MAXTILE 136

// ---------------- scratch (static device memory, no runtime alloc) ----------
__device__ float g_xln[(size_t)TOK*DD];               // fp32 LN out (gate reads; LN3 only)
__device__ __nv_bfloat16 g_xh[(size_t)TOK*DD];        // split LN out
__device__ __nv_bfloat16 g_xl[(size_t)TOK*DD];
__device__ __nv_bfloat16 g_qkvh[(size_t)TOK*3*DD];    // split qkv (hi)
__device__ __nv_bfloat16 g_qkvl[(size_t)TOK*3*DD];    // split qkv (lo)
__device__ __nv_bfloat16 g_ah[(size_t)TOK*DD];        // split attention out
__device__ __nv_bfloat16 g_al[(size_t)TOK*DD];
__device__ float g_x[(size_t)TOK*DD];                 // running residual (fp32)
__device__ __nv_bfloat16 g_xrh[(size_t)TOK*DD];       // split post-MoE residual
__device__ __nv_bfloat16 g_xrl[(size_t)TOK*DD];
__device__ float g_moey[(size_t)NE*TOK*DD];
__device__ __nv_bfloat16 g_hh[(size_t)TOK*FFH];       // split FF hidden
__device__ __nv_bfloat16 g_hl[(size_t)TOK*FFH];
__device__ int2   g_topi[TOK];
__device__ float2 g_topw[TOK];
__device__ float  g_ent[TOK];

// sparse MoE routing state
__device__ int g_cnt[NE];
__device__ int g_idxflat[NE*TOK];
__device__ int g_pos[2*TOK];
__device__ int g_tile_rb[MAXTILE];
__device__ int g_tile_cnt[MAXTILE];
__device__ int g_tile_e[MAXTILE];
__device__ int g_ntiles;

// transposed + split bf16 weights  [N][K] layout
#define OFF_QKV  0u
#define OFF_ATT  3145728u
#define OFF_CONV 4194304u
#define OFF_EXP  7340032u
#define OFF_FF1  15728640u
#define OFF_FF2  19922944u
#define WT_TOTAL 24117248u
__device__ __nv_bfloat16 g_wh[WT_TOTAL];
__device__ __nv_bfloat16 g_wl[WT_TOTAL];

__device__ __forceinline__ float gelu_exact(float x) {
    return 0.5f * x * (1.0f + erff(x * 0.70710678118654752f));
}

__device__ __forceinline__ uint32_t smem_u32(const void* p) {
    uint32_t a;
    asm("{ .reg .u64 t; cvta.to.shared.u64 t, %1; cvt.u32.u64 %0, t; }" : "=r"(a) : "l"(p));
    return a;
}

__device__ __forceinline__ void ldm_x4(uint32_t* r, uint32_t addr) {
    asm volatile("ldmatrix.sync.aligned.m8n8.x4.shared.b16 {%0,%1,%2,%3}, [%4];"
                 : "=r"(r[0]), "=r"(r[1]), "=r"(r[2]), "=r"(r[3]) : "r"(addr));
}

__device__ __forceinline__ void ldm_x4_t(uint32_t* r, uint32_t addr) {
    asm volatile("ldmatrix.sync.aligned.m8n8.x4.trans.shared.b16 {%0,%1,%2,%3}, [%4];"
                 : "=r"(r[0]), "=r"(r[1]), "=r"(r[2]), "=r"(r[3]) : "r"(addr));
}

__device__ __forceinline__ void mma_bf16(float* d, const uint32_t* a, const uint32_t* b) {
    asm volatile(
        "mma.sync.aligned.m16n8k16.row.col.f32.bf16.bf16.f32 "
        "{%0,%1,%2,%3}, {%4,%5,%6,%7}, {%8,%9}, {%0,%1,%2,%3};"
        : "+f"(d[0]), "+f"(d[1]), "+f"(d[2]), "+f"(d[3])
        : "r"(a[0]), "r"(a[1]), "r"(a[2]), "r"(a[3]), "r"(b[0]), "r"(b[1]));
}

#define CP16(dst, src) \
    asm volatile("cp.async.cg.shared.global [%0], [%1], 16;" :: "r"(dst), "l"(src))
#define CP16Z(dst, src, sz) \
    asm volatile("cp.async.cg.shared.global [%0], [%1], 16, %2;" :: "r"(dst), "l"(src), "r"(sz))
#define CP_COMMIT() asm volatile("cp.async.commit_group;" ::: "memory")
#define CP_WAIT(n)  asm volatile("cp.async.wait_group %0;" :: "n"(n) : "memory")

__device__ __forceinline__ void split2(float a, float b, uint32_t& hi, uint32_t& lo) {
    __nv_bfloat16 ha = __float2bfloat16_rn(a), hb = __float2bfloat16_rn(b);
    float ra = a - __bfloat162float(ha), rb = b - __bfloat162float(hb);
    __nv_bfloat16 la = __float2bfloat16_rn(ra), lb = __float2bfloat16_rn(rb);
    hi = (uint32_t)__bfloat16_as_ushort(ha) | ((uint32_t)__bfloat16_as_ushort(hb) << 16);
    lo = (uint32_t)__bfloat16_as_ushort(la) | ((uint32_t)__bfloat16_as_ushort(lb) << 16);
}

// ---------------- shared GEMM machinery (R9 config, single-barrier mainloop) -----
// 128x128 tile, 8 warps (2x4), warp tile 64x32, K-chunk 32, 2-stage, 2 CTA/SM.
#define ROWB   80
#define ASZ    10240          // 128 * 80
#define STAGE  40960          // A_h + A_l + B_h + B_l
#define GEMM_SMEM (2 * STAGE) // 81920

struct GemmCtx {
    uint32_t sb, foff, aoff, boff;
    int lane, wm, wn, frow, fhalf;
};

__device__ __forceinline__ void gemm_setup(GemmCtx& g, char* sm) {
    const int tid = threadIdx.x;
    g.sb = smem_u32(sm);
    g.lane = tid & 31;
    const int wid = tid >> 5;
    g.wm = wid >> 2; g.wn = wid & 3;
    g.frow = tid >> 1; g.fhalf = tid & 1;
    g.foff = (uint32_t)(g.frow * ROWB + g.fhalf * 32);
    g.aoff = (uint32_t)((g.wm * 64 + (g.lane & 15)) * ROWB + (g.lane >> 4) * 16);
    const int bgroup = g.lane >> 3, bwithin = g.lane & 7;
    g.boff = (uint32_t)((g.wn * 32 + (bgroup >> 1) * 8 + bwithin) * ROWB + (bgroup & 1) * 16);
}

__device__ __forceinline__ void cp_pair(uint32_t dst_h, uint32_t dst_l,
                                        const __nv_bfloat16* src_h,
                                        const __nv_bfloat16* src_l) {
    CP16(dst_h,      (const char*)src_h);
    CP16(dst_h + 16, (const char*)src_h + 16);
    CP16(dst_l,      (const char*)src_l);
    CP16(dst_l + 16, (const char*)src_l + 16);
}

__device__ __forceinline__ void compute_stage(const GemmCtx& g, int buf,
                                              float acc[4][4][4]) {
    const uint32_t sA_h = g.sb + buf * STAGE;
    const uint32_t sA_l = sA_h + ASZ;
    const uint32_t sB_h = sA_h + 2 * ASZ;
    const uint32_t sB_l = sA_h + 3 * ASZ;
    #pragma unroll
    for (int ks = 0; ks < 2; ks++) {
        uint32_t Ah[4][4], Al[4][4], Bhf[4][2], Blf[4][2];
        #pragma unroll
        for (int mt = 0; mt < 4; mt++) {
            ldm_x4(Ah[mt], sA_h + g.aoff + mt * (16 * ROWB) + ks * 32);
            ldm_x4(Al[mt], sA_l + g.aoff + mt * (16 * ROWB) + ks * 32);
        }
        #pragma unroll
        for (int n2 = 0; n2 < 2; n2++) {
            uint32_t r[4];
            ldm_x4(r, sB_h + g.boff + n2 * (16 * ROWB) + ks * 32);
            Bhf[n2*2][0] = r[0]; Bhf[n2*2][1] = r[1];
            Bhf[n2*2+1][0] = r[2]; Bhf[n2*2+1][1] = r[3];
            ldm_x4(r, sB_l + g.boff + n2 * (16 * ROWB) + ks * 32);
            Blf[n2*2][0] = r[0]; Blf[n2*2][1] = r[1];
            Blf[n2*2+1][0] = r[2]; Blf[n2*2+1][1] = r[3];
        }
        #pragma unroll
        for (int mt = 0; mt < 4; mt++)
            #pragma unroll
            for (int nt = 0; nt < 4; nt++) {
                mma_bf16(acc[mt][nt], Ah[mt], Bhf[nt]);
                mma_bf16(acc[mt][nt], Ah[mt], Blf[nt]);
                mma_bf16(acc[mt][nt], Al[mt], Bhf[nt]);
            }
    }
}

// single-barrier 2-stage mainloop:
//   WAIT(0)  -> group s complete (fills buf)
//   sync     -> fills visible to all threads AND all threads done computing buf^1
//   issue(s+1, buf^1)   (safe: everyone finished reading buf^1)
//   compute(buf)        (overlaps group s+1's cp.async)
#define MAINLOOP_1BAR(nst, ISSUE)                     \
    ISSUE(0, 0);                                      \
    for (int s = 0; s < (nst); s++) {                 \
        const int buf = s & 1;                        \
        CP_WAIT(0);                                   \
        __syncthreads();                              \
        if (s + 1 < (nst)) ISSUE(s + 1, buf ^ 1);     \
        compute_stage(g, buf, acc);                   \
    }

// ---------------- standard GEMM ---------------------------------------------------
template<bool GELU, bool RESID, bool OSPLIT>
__global__ void __launch_bounds__(256, 2) gemm_mma(const __nv_bfloat16* __restrict__ Ah,
                                                   const __nv_bfloat16* __restrict__ Al,
                                                   const __nv_bfloat16* __restrict__ Bh,
                                                   const __nv_bfloat16* __restrict__ Bl,
                                                   const float* __restrict__ bias,
                                                   const float* __restrict__ R,
                                                   float* __restrict__ C,
                                                   __nv_bfloat16* __restrict__ Oh,
                                                   __nv_bfloat16* __restrict__ Ol,
                                                   int M, int N, int K) {
    extern __shared__ char sm[];
    GemmCtx g; gemm_setup(g, sm);
    const int bm = blockIdx.y * 128, bn = blockIdx.x * 128;

    const __nv_bfloat16* Ahp = Ah + (size_t)(bm + g.frow) * K + g.fhalf * 16;
    const __nv_bfloat16* Alp = Al + (size_t)(bm + g.frow) * K + g.fhalf * 16;
    const __nv_bfloat16* Bhp = Bh + (size_t)(bn + g.frow) * K + g.fhalf * 16;
    const __nv_bfloat16* Blp = Bl + (size_t)(bn + g.frow) * K + g.fhalf * 16;

    float acc[4][4][4] = {};
    const int nst = K >> 5;

    auto issue = [&](int s, int buf) {
        const int k0 = s << 5;
        const uint32_t base = g.sb + buf * STAGE;
        cp_pair(base + g.foff,         base + ASZ + g.foff,   Ahp + k0, Alp + k0);
        cp_pair(base + 2*ASZ + g.foff, base + 3*ASZ + g.foff, Bhp + k0, Blp + k0);
        CP_COMMIT();
    };

    MAINLOOP_1BAR(nst, issue)

    const int r0base = bm + g.wm * 64 + (g.lane >> 2);
    const int cbase = bn + g.wn * 32 + (g.lane & 3) * 2;
    #pragma unroll
    for (int mt = 0; mt < 4; mt++) {
        #pragma unroll
        for (int nt = 0; nt < 4; nt++) {
            const int c = cbase + nt * 8;
            const float2 bb = *(const float2*)(bias + c);
            const int r0 = r0base + mt * 16;
            const int r1 = r0 + 8;
            float2 v0, v1;
            v0.x = acc[mt][nt][0] + bb.x; v0.y = acc[mt][nt][1] + bb.y;
            v1.x = acc[mt][nt][2] + bb.x; v1.y = acc[mt][nt][3] + bb.y;
            if (GELU) {
                v0.x = gelu_exact(v0.x); v0.y = gelu_exact(v0.y);
                v1.x = gelu_exact(v1.x); v1.y = gelu_exact(v1.y);
            }
            if (RESID) {
                const float2 q0 = *(const float2*)(R + (size_t)r0 * N + c);
                const float2 q1 = *(const float2*)(R + (size_t)r1 * N + c);
                v0.x += q0.x; v0.y += q0.y; v1.x += q1.x; v1.y += q1.y;
            }
            if (OSPLIT) {
                uint32_t h0, l0, h1, l1;
                split2(v0.x, v0.y, h0, l0);
                split2(v1.x, v1.y, h1, l1);
                *(uint32_t*)(Oh + (size_t)r0 * N + c) = h0;
                *(uint32_t*)(Ol + (size_t)r0 * N + c) = l0;
                *(uint32_t*)(Oh + (size_t)r1 * N + c) = h1;
                *(uint32_t*)(Ol + (size_t)r1 * N + c) = l1;
            } else {
                *(float2*)(C + (size_t)r0 * N + c) = v0;
                *(float2*)(C + (size_t)r1 * N + c) = v1;
            }
        }
    }
}

// ---------------- conv GEMM with fused dilated im2col gather -------------------
__global__ void __launch_bounds__(256, 2) gemm_conv(const __nv_bfloat16* __restrict__ xh,
                                                    const __nv_bfloat16* __restrict__ xl,
                                                    const __nv_bfloat16* __restrict__ Bh,
                                                    const __nv_bfloat16* __restrict__ Bl,
                                                    const float* __restrict__ bias,
                                                    float* __restrict__ C) {
    extern __shared__ char sm[];
    GemmCtx g; gemm_setup(g, sm);
    const int bm = blockIdx.y * 128, bn = blockIdx.x * 128;
    const int N = DD, K = 3 * DD;

    const int t = bm + g.frow;
    const int b = t >> 12, l = t & (LL - 1);
    const __nv_bfloat16* Bhp = Bh + (size_t)(bn + g.frow) * K + g.fhalf * 16;
    const __nv_bfloat16* Blp = Bl + (size_t)(bn + g.frow) * K + g.fhalf * 16;

    float acc[4][4][4] = {};
    const int nst = K >> 5;  // 96

    auto issue = [&](int s, int buf) {
        const int k0 = s << 5;
        const uint32_t base = g.sb + buf * STAGE;
        const int kk = k0 + g.fhalf * 16;
        const int tap = kk >> 10, din = kk & 1023;
        const int ls = l + 2 * tap - 2;
        const int ok = ((unsigned)ls < (unsigned)LL) ? 16 : 0;
        const int lsc = min(max(ls, 0), LL - 1);
        const size_t abase = ((size_t)(b * LL + lsc)) * DD + din;
        const char* sah = (const char*)(xh + abase);
        const char* sal = (const char*)(xl + abase);
        CP16Z(base + g.foff,            sah,      ok);
        CP16Z(base + g.foff + 16,       sah + 16, ok);
        CP16Z(base + ASZ + g.foff,      sal,      ok);
        CP16Z(base + ASZ + g.foff + 16, sal + 16, ok);
        cp_pair(base + 2*ASZ + g.foff, base + 3*ASZ + g.foff, Bhp + k0, Blp + k0);
        CP_COMMIT();
    };

    MAINLOOP_1BAR(nst, issue)

    const int r0base = bm + g.wm * 64 + (g.lane >> 2);
    const int cbase = bn + g.wn * 32 + (g.lane & 3) * 2;
    #pragma unroll
    for (int mt = 0; mt < 4; mt++) {
        #pragma unroll
        for (int nt = 0; nt < 4; nt++) {
            const int c = cbase + nt * 8;
            const float2 bb = *(const float2*)(bias + c);
            const int r0 = r0base + mt * 16;
            const int r1 = r0 + 8;
            const float2 q0 = *(const float2*)(C + (size_t)r0 * N + c);
            const float2 q1 = *(const float2*)(C + (size_t)r1 * N + c);
            float2 v0, v1;
            v0.x = acc[mt][nt][0] + bb.x + q0.x; v0.y = acc[mt][nt][1] + bb.y + q0.y;
            v1.x = acc[mt][nt][2] + bb.x + q1.x; v1.y = acc[mt][nt][3] + bb.y + q1.y;
            *(float2*)(C + (size_t)r0 * N + c) = v0;
            *(float2*)(C + (size_t)r1 * N + c) = v1;
        }
    }
}

// ---------------- sparse MoE grouped GEMM ---------------------------------------
__global__ void __launch_bounds__(256, 2) gemm_moe(const __nv_bfloat16* __restrict__ xh,
                                                   const __nv_bfloat16* __restrict__ xl,
                                                   const __nv_bfloat16* __restrict__ WhBase,
                                                   const __nv_bfloat16* __restrict__ WlBase,
                                                   const float* __restrict__ ebias,
                                                   float* __restrict__ Y) {
    if ((int)blockIdx.y >= g_ntiles) return;
    extern __shared__ char sm[];
    GemmCtx g; gemm_setup(g, sm);
    const int rb = g_tile_rb[blockIdx.y];
    const int tcnt = g_tile_cnt[blockIdx.y];
    const int e = g_tile_e[blockIdx.y];
    const int bn = blockIdx.x * 128;
    const int N = DD, K = DD;

    const int tok = g_idxflat[rb + g.frow];
    const __nv_bfloat16* Ahp = xh + (size_t)tok * K + g.fhalf * 16;
    const __nv_bfloat16* Alp = xl + (size_t)tok * K + g.fhalf * 16;
    const __nv_bfloat16* Bhp = WhBase + (size_t)e * DD * DD + (size_t)(bn + g.frow) * K + g.fhalf * 16;
    const __nv_bfloat16* Blp = WlBase + (size_t)e * DD * DD + (size_t)(bn + g.frow) * K + g.fhalf * 16;
    const float* bias = ebias + (size_t)e * DD;

    float acc[4][4][4] = {};
    const int nst = K >> 5;

    auto issue = [&](int s, int buf) {
        const int k0 = s << 5;
        const uint32_t base = g.sb + buf * STAGE;
        cp_pair(base + g.foff,         base + ASZ + g.foff,   Ahp + k0, Alp + k0);
        cp_pair(base + 2*ASZ + g.foff, base + 3*ASZ + g.foff, Bhp + k0, Blp + k0);
        CP_COMMIT();
    };

    MAINLOOP_1BAR(nst, issue)

    const int lrbase = g.wm * 64 + (g.lane >> 2);
    const int cbase = bn + g.wn * 32 + (g.lane & 3) * 2;
    #pragma unroll
    for (int mt = 0; mt < 4; mt++) {
        #pragma unroll
        for (int nt = 0; nt < 4; nt++) {
            const int c = cbase + nt * 8;
            const float2 bb = *(const float2*)(bias + c);
            const int lr0 = lrbase + mt * 16;
            const int lr1 = lr0 + 8;
            float2 v0, v1;
            v0.x = gelu_exact(acc[mt][nt][0] + bb.x);
            v0.y = gelu_exact(acc[mt][nt][1] + bb.y);
            v1.x = gelu_exact(acc[mt][nt][2] + bb.x);
            v1.y = gelu_exact(acc[mt][nt][3] + bb.y);
            if (lr0 < tcnt) *(float2*)(Y + (size_t)(rb + lr0) * N + c) = v0;
            if (lr1 < tcnt) *(float2*)(Y + (size_t)(rb + lr1) * N + c) = v1;
        }
    }
}

// ---------------- tensor-core windowed flash attention --------------------------
#define AROWB 144
__global__ void __launch_bounds__(256) attn_tc(const __nv_bfloat16* __restrict__ qh,
                                               const __nv_bfloat16* __restrict__ ql,
                                               __nv_bfloat16* __restrict__ oh,
                                               __nv_bfloat16* __restrict__ ol) {
    __shared__ char smn[4 * 32 * AROWB];   // Kh, Kl, Vh, Vl (32 x 144B each)
    const int h = blockIdx.x & 15;
    const int w = (blockIdx.x >> 4) & 15;
    const int b = blockIdx.x >> 8;
    const int t0 = b * LL + w * WIN;
    const int tid = threadIdx.x, lane = tid & 31, wid = tid >> 5;
    const int gid = lane >> 2, tig = lane & 3;
    const uint32_t sb = smem_u32(smn);
    const uint32_t sKh = sb, sKl = sb + 4608, sVh = sb + 9216, sVl = sb + 13824;

    uint32_t Qh[2][4][4], Ql[2][4][4];
    #pragma unroll
    for (int mt = 0; mt < 2; mt++) {
        const int r0 = t0 + wid * 32 + mt * 16 + gid;
        const size_t q0 = (size_t)r0 * 3072 + h * 64;
        const size_t q1 = q0 + (size_t)8 * 3072;
        #pragma unroll
        for (int kk = 0; kk < 4; kk++) {
            const int c = kk * 16 + 2 * tig;
            Qh[mt][kk][0] = *(const uint32_t*)(qh + q0 + c);
            Ql[mt][kk][0] = *(const uint32_t*)(ql + q0 + c);
            Qh[mt][kk][1] = *(const uint32_t*)(qh + q1 + c);
            Ql[mt][kk][1] = *(const uint32_t*)(ql + q1 + c);
            Qh[mt][kk][2] = *(const uint32_t*)(qh + q0 + c + 8);
            Ql[mt][kk][2] = *(const uint32_t*)(ql + q0 + c + 8);
            Qh[mt][kk][3] = *(const uint32_t*)(qh + q1 + c + 8);
            Ql[mt][kk][3] = *(const uint32_t*)(ql + q1 + c + 8);
        }
    }

    float o[2][8][4] = {};
    float mrun[2][2] = {{-1e30f, -1e30f}, {-1e30f, -1e30f}};
    float lrun[2][2] = {};

    const int stok = tid >> 3, sq = tid & 7;
    const size_t kvoff = (size_t)(t0 + stok) * 3072 + 1024 + h * 64 + sq * 8;
    const uint32_t soff = (uint32_t)(stok * AROWB + sq * 16);

    const uint32_t kaddr = (uint32_t)((((lane >> 4) & 1) * 8 + (lane & 7)) * AROWB
                                      + ((lane >> 3) & 1) * 16);

    for (int c8 = 0; c8 < 8; c8++) {
        __syncthreads();
        {
            const size_t kbase = kvoff + (size_t)(c8 * 32) * 3072;
            *(uint4*)(smn + soff)         = *(const uint4*)(qh + kbase);
            *(uint4*)(smn + 4608 + soff)  = *(const uint4*)(ql + kbase);
            *(uint4*)(smn + 9216 + soff)  = *(const uint4*)(qh + kbase + 1024);
            *(uint4*)(smn + 13824 + soff) = *(const uint4*)(ql + kbase + 1024);
        }
        __syncthreads();

        float s[2][4][4] = {};
        #pragma unroll
        for (int kk = 0; kk < 4; kk++) {
            #pragma unroll
            for (int n2 = 0; n2 < 2; n2++) {
                uint32_t rbh[4], rbl[4];
                const uint32_t a = kaddr + (uint32_t)(n2 * 16 * AROWB + kk * 32);
                ldm_x4(rbh, sKh + a);
                ldm_x4(rbl, sKl + a);
                #pragma unroll
                for (int mt = 0; mt < 2; mt++) {
                    mma_bf16(s[mt][n2*2],   Qh[mt][kk], rbh);
                    mma_bf16(s[mt][n2*2],   Qh[mt][kk], rbl);
                    mma_bf16(s[mt][n2*2],   Ql[mt][kk], rbh);
                    mma_bf16(s[mt][n2*2+1], Qh[mt][kk], rbh + 2);
                    mma_bf16(s[mt][n2*2+1], Qh[mt][kk], rbl + 2);
                    mma_bf16(s[mt][n2*2+1], Ql[mt][kk], rbh + 2);
                }
            }
        }

        uint32_t Ph[2][2][4], Pl[2][2][4];
        #pragma unroll
        for (int mt = 0; mt < 2; mt++) {
            float m0 = -1e30f, m1 = -1e30f;
            #pragma unroll
            for (int nt = 0; nt < 4; nt++) {
                #pragma unroll
                for (int i = 0; i < 4; i++) s[mt][nt][i] *= 0.125f;
                m0 = fmaxf(m0, fmaxf(s[mt][nt][0], s[mt][nt][1]));
                m1 = fmaxf(m1, fmaxf(s[mt][nt][2], s[mt][nt][3]));
            }
            m0 = fmaxf(m0, __shfl_xor_sync(0xffffffffu, m0, 1));
            m0 = fmaxf(m0, __shfl_xor_sync(0xffffffffu, m0, 2));
            m1 = fmaxf(m1, __shfl_xor_sync(0xffffffffu, m1, 1));
            m1 = fmaxf(m1, __shfl_xor_sync(0xffffffffu, m1, 2));
            const float mn0 = fmaxf(mrun[mt][0], m0);
            const float mn1 = fmaxf(mrun[mt][1], m1);
            const float f0 = __expf(mrun[mt][0] - mn0);
            const float f1 = __expf(mrun[mt][1] - mn1);
            mrun[mt][0] = mn0; mrun[mt][1] = mn1;
            float l0 = 0.f, l1 = 0.f;
            #pragma unroll
            for (int nt = 0; nt < 4; nt++) {
                s[mt][nt][0] = __expf(s[mt][nt][0] - mn0);
                s[mt][nt][1] = __expf(s[mt][nt][1] - mn0);
                s[mt][nt][2] = __expf(s[mt][nt][2] - mn1);
                s[mt][nt][3] = __expf(s[mt][nt][3] - mn1);
                l0 += s[mt][nt][0] + s[mt][nt][1];
                l1 += s[mt][nt][2] + s[mt][nt][3];
            }
            l0 += __shfl_xor_sync(0xffffffffu, l0, 1);
            l0 += __shfl_xor_sync(0xffffffffu, l0, 2);
            l1 += __shfl_xor_sync(0xffffffffu, l1, 1);
            l1 += __shfl_xor_sync(0xffffffffu, l1, 2);
            lrun[mt][0] = lrun[mt][0] * f0 + l0;
            lrun[mt][1] = lrun[mt][1] * f1 + l1;
            #pragma unroll
            for (int nt = 0; nt < 8; nt++) {
                o[mt][nt][0] *= f0; o[mt][nt][1] *= f0;
                o[mt][nt][2] *= f1; o[mt][nt][3] *= f1;
            }
            #pragma unroll
            for (int kk2 = 0; kk2 < 2; kk2++) {
                split2(s[mt][2*kk2][0],   s[mt][2*kk2][1],   Ph[mt][kk2][0], Pl[mt][kk2][0]);
                split2(s[mt][2*kk2][2],   s[mt][2*kk2][3],   Ph[mt][kk2][1], Pl[mt][kk2][1]);
                split2(s[mt][2*kk2+1][0], s[mt][2*kk2+1][1], Ph[mt][kk2][2], Pl[mt][kk2][2]);
                split2(s[mt][2*kk2+1][2], s[mt][2*kk2+1][3], Ph[mt][kk2][3], Pl[mt][kk2][3]);
            }
        }

        #pragma unroll
        for (int dp = 0; dp < 4; dp++) {
            #pragma unroll
            for (int kk2 = 0; kk2 < 2; kk2++) {
                uint32_t vbh[4], vbl[4];
                const uint32_t va = (uint32_t)((kk2 * 16 + (lane & 7) + ((lane >> 3) & 1) * 8) * AROWB
                                               + (dp * 2 + ((lane >> 4) & 1)) * 16);
                ldm_x4_t(vbh, sVh + va);
                ldm_x4_t(vbl, sVl + va);
                #pragma unroll
                for (int mt = 0; mt < 2; mt++) {
                    mma_bf16(o[mt][dp*2],   Ph[mt][kk2], vbh);
                    mma_bf16(o[mt][dp*2],   Ph[mt][kk2], vbl);
                    mma_bf16(o[mt][dp*2],   Pl[mt][kk2], vbh);
                    mma_bf16(o[mt][dp*2+1], Ph[mt][kk2], vbh + 2);
                    mma_bf16(o[mt][dp*2+1], Ph[mt][kk2], vbl + 2);
                    mma_bf16(o[mt][dp*2+1], Pl[mt][kk2], vbh + 2);
                }
            }
        }
    }

    #pragma unroll
    for (int mt = 0; mt < 2; mt++) {
        const float i0 = 1.f / lrun[mt][0], i1 = 1.f / lrun[mt][1];
        const int r0 = t0 + wid * 32 + mt * 16 + gid;
        #pragma unroll
        for (int nt = 0; nt < 8; nt++) {
            const int c = h * 64 + nt * 8 + 2 * tig;
            uint32_t ph, pl;
            split2(o[mt][nt][0] * i0, o[mt][nt][1] * i0, ph, pl);
            *(uint32_t*)(oh + (size_t)r0 * 1024 + c) = ph;
            *(uint32_t*)(ol + (size_t)r0 * 1024 + c) = pl;
            split2(o[mt][nt][2] * i1, o[mt][nt][3] * i1, ph, pl);
            *(uint32_t*)(oh + (size_t)(r0 + 8) * 1024 + c) = ph;
            *(uint32_t*)(ol + (size_t)(r0 + 8) * 1024 + c) = pl;
        }
    }
}

// ---------------- weight transpose + bf16 split ---------------------------------
__global__ void __launch_bounds__(256) wt_kernel(const float* __restrict__ W,
                                                 __nv_bfloat16* __restrict__ Th,
                                                 __nv_bfloat16* __restrict__ Tl,
                                                 int K, int N) {
    __shared__ float tile[32][33];
    const size_t slab = (size_t)blockIdx.z * K * N;
    const int k0 = blockIdx.y * 32, n0 = blockIdx.x * 32;
    const int x = threadIdx.x, y = threadIdx.y;
    #pragma unroll
    for (int j = 0; j < 32; j += 8)
        tile[y + j][x] = W[slab + (size_t)(k0 + y + j) * N + n0 + x];
    __syncthreads();
    #pragma unroll
    for (int j = 0; j < 32; j += 8) {
        const float v = tile[x][y + j];
        const int n = n0 + y + j, k = k0 + x;
        const __nv_bfloat16 h = __float2bfloat16_rn(v);
        Th[slab + (size_t)n * K + k] = h;
        Tl[slab + (size_t)n * K + k] = __float2bfloat16_rn(v - __bfloat162float(h));
    }
}

__global__ void __launch_bounds__(256) convw_t(const float* __restrict__ cw,
                                               __nv_bfloat16* __restrict__ Th,
                                               __nv_bfloat16* __restrict__ Tl) {
    const size_t idx = (size_t)blockIdx.x * 256 + threadIdx.x;
    const int dout = (int)(idx / 3072);
    const int r = (int)(idx % 3072);
    const int tap = r >> 10, din = r & 1023;
    const float v = cw[((size_t)dout * DD + din) * 3 + tap];
    const __nv_bfloat16 h = __float2bfloat16_rn(v);
    Th[idx] = h;
    Tl[idx] = __float2bfloat16_rn(v - __bfloat162float(h));
}

// ---------------- LayerNorm (optional fp32 + split bf16 outputs) -----------------
__global__ void __launch_bounds__(256) ln_kernel(const float* __restrict__ x,
                                                 const float* __restrict__ g,
                                                 const float* __restrict__ b,
                                                 float* __restrict__ y,
                                                 __nv_bfloat16* __restrict__ yh,
                                                 __nv_bfloat16* __restrict__ yl) {
    __shared__ float red[8];
    __shared__ float sh_mu, sh_inv;
    const int tid = threadIdx.x, lane = tid & 31, warp = tid >> 5;
    const float4 xv = ((const float4*)(x + (size_t)blockIdx.x * DD))[tid];

    float s = xv.x + xv.y + xv.z + xv.w;
    #pragma unroll
    for (int o = 16; o > 0; o >>= 1) s += __shfl_down_sync(0xffffffffu, s, o);
    if (lane == 0) red[warp] = s;
    __syncthreads();
    if (tid == 0) {
        float t = 0.f;
        #pragma unroll
        for (int i = 0; i < 8; i++) t += red[i];
        sh_mu = t * (1.0f / DD);
    }
    __syncthreads();
    const float mu = sh_mu;
    const float dx = xv.x - mu, dy = xv.y - mu, dz = xv.z - mu, dw = xv.w - mu;
    float s2 = dx*dx + dy*dy + dz*dz + dw*dw;
    #pragma unroll
    for (int o = 16; o > 0; o >>= 1) s2 += __shfl_down_sync(0xffffffffu, s2, o);
    if (lane == 0) red[warp] = s2;
    __syncthreads();
    if (tid == 0) {
        float t = 0.f;
        #pragma unroll
        for (int i = 0; i < 8; i++) t += red[i];
        sh_inv = rsqrtf(t * (1.0f / DD) + 1e-5f);
    }
    __syncthreads();
    const float inv = sh_inv;
    const float4 gv = ((const float4*)g)[tid];
    const float4 bv = ((const float4*)b)[tid];
    float4 o;
    o.x = dx * inv * gv.x + bv.x;
    o.y = dy * inv * gv.y + bv.y;
    o.z = dz * inv * gv.z + bv.z;
    o.w = dw * inv * gv.w + bv.w;
    const size_t idx = (size_t)blockIdx.x * DD + tid * 4;
    if (y) *(float4*)(y + idx) = o;
    uint32_t h0, l0, h1, l1;
    split2(o.x, o.y, h0, l0);
    split2(o.z, o.w, h1, l1);
    *(uint32_t*)(yh + idx)     = h0;
    *(uint32_t*)(yh + idx + 2) = h1;
    *(uint32_t*)(yl + idx)     = l0;
    *(uint32_t*)(yl + idx + 2) = l1;
}

// ---------------- gate: softmax, entropy, top-2 ---------------------------------
__global__ void __launch_bounds__(256) gate_kernel(const float* __restrict__ xln,
                                                   const float* __restrict__ gw,
                                                   const float* __restrict__ gb) {
    if (blockIdx.x == 0 && threadIdx.x < NE) g_cnt[threadIdx.x] = 0;
    const int warp = threadIdx.x >> 5, lane = threadIdx.x & 31;
    const int t = blockIdx.x * 8 + warp;
    const float* xr = xln + (size_t)t * DD;

    float a[8] = {0.f,0.f,0.f,0.f,0.f,0.f,0.f,0.f};
    for (int i = lane; i < DD; i += 32) {
        const float xv = xr[i];
        const float* g8 = gw + i * 8;
        #pragma unroll
        for (int e = 0; e < 8; e++) a[e] += xv * g8[e];
    }
    #pragma unroll
    for (int e = 0; e < 8; e++) {
        #pragma unroll
        for (int o = 16; o > 0; o >>= 1) a[e] += __shfl_down_sync(0xffffffffu, a[e], o);
    }
    if (lane == 0) {
        float lg[8], mx = -1e30f;
        #pragma unroll
        for (int e = 0; e < 8; e++) { lg[e] = a[e] + gb[e]; mx = fmaxf(mx, lg[e]); }
        float p[8], den = 0.f;
        #pragma unroll
        for (int e = 0; e < 8; e++) { p[e] = expf(lg[e] - mx); den += p[e]; }
        float ent = 0.f;
        #pragma unroll
        for (int e = 0; e < 8; e++) { p[e] /= den; ent -= p[e] * logf(p[e] + 1e-10f); }
        g_ent[t] = ent;

        int i0 = 0; float v0 = p[0];
        #pragma unroll
        for (int e = 1; e < 8; e++) if (p[e] > v0) { v0 = p[e]; i0 = e; }
        int i1 = -1; float v1 = -1e30f;
        #pragma unroll
        for (int e = 0; e < 8; e++) if (e != i0 && p[e] > v1) { v1 = p[e]; i1 = e; }
        const float sw = v0 + v1;
        g_topi[t] = make_int2(i0, i1);
        g_topw[t] = make_float2(v0 / sw, v1 / sw);
    }
}

// ---------------- routing kernels -------------------------------------------------
__global__ void __launch_bounds__(256) scatter_kernel() {
    const int t = blockIdx.x * 256 + threadIdx.x;
    if (t >= TOK) return;
    const int2 ii = g_topi[t];
    const int p0 = atomicAdd(&g_cnt[ii.x], 1);
    g_idxflat[ii.x * TOK + p0] = t;
    g_pos[2 * t] = ii.x * TOK + p0;
    const int p1 = atomicAdd(&g_cnt[ii.y], 1);
    g_idxflat[ii.y * TOK + p1] = t;
    g_pos[2 * t + 1] = ii.y * TOK + p1;
}

__global__ void __launch_bounds__(256) tile_build() {
    __shared__ int scnt[NE];
    if (threadIdx.x < NE) scnt[threadIdx.x] = g_cnt[threadIdx.x];
    __syncthreads();
    if (threadIdx.x == 0) {
        int nt = 0;
        for (int e = 0; e < NE; e++) {
            const int c = scnt[e];
            const int t = (c + 127) >> 7;
            for (int i = 0; i < t; i++) {
                g_tile_rb[nt] = e * TOK + i * 128;
                g_tile_cnt[nt] = min(128, c - i * 128);
                g_tile_e[nt] = e;
                nt++;
            }
        }
        g_ntiles = nt;
    }
    for (int j = threadIdx.x; j < NE * 128; j += 256) {
        const int e = j >> 7;
        const int c = scnt[e];
        const int off = c + (j & 127);
        const int lim = ((c + 127) >> 7) << 7;
        if (off < lim) g_idxflat[e * TOK + off] = 0;
    }
}

// ---------------- MoE combine: update fp32 resid + emit split ------------------
__global__ void __launch_bounds__(256) combine_kernel(const float* __restrict__ Y,
                                                      float* __restrict__ x,
                                                      __nv_bfloat16* __restrict__ xh,
                                                      __nv_bfloat16* __restrict__ xl) {
    const int t = blockIdx.x;
    const int d = threadIdx.x * 4;
    const int p0 = g_pos[2 * t], p1 = g_pos[2 * t + 1];
    const float2 ww = g_topw[t];
    const float4 a = *(const float4*)(Y + (size_t)p0 * DD + d);
    const float4 b = *(const float4*)(Y + (size_t)p1 * DD + d);
    const size_t idx = (size_t)t * DD + d;
    float4 xv = *(float4*)(x + idx);
    xv.x += ww.x * a.x + ww.y * b.x;
    xv.y += ww.x * a.y + ww.y * b.y;
    xv.z += ww.x * a.z + ww.y * b.z;
    xv.w += ww.x * a.w + ww.y * b.w;
    *(float4*)(x + idx) = xv;
    uint32_t h0, l0, h1, l1;
    split2(xv.x, xv.y, h0, l0);
    split2(xv.z, xv.w, h1, l1);
    *(uint32_t*)(xh + idx)     = h0;
    *(uint32_t*)(xh + idx + 2) = h1;
    *(uint32_t*)(xl + idx)     = l0;
    *(uint32_t*)(xl + idx + 2) = l1;
}

// ---------------- deterministic entropy reduction -------------------------------
__global__ void __launch_bounds__(256) ent_reduce(float* __restrict__ out) {
    __shared__ float sm[256];
    float s = 0.f;
    for (int i = threadIdx.x; i < TOK; i += 256) s += g_ent[i];
    sm[threadIdx.x] = s;
    __syncthreads();
    #pragma unroll
    for (int o = 128; o > 0; o >>= 1) {
        if (threadIdx.x < o) sm[threadIdx.x] += sm[threadIdx.x + o];
        __syncthreads();
    }
    if (threadIdx.x == 0) out[0] = 0.1f * sm[0] / (float)TOK;
}

// ---------------- launch ----------------------------------------------------------
extern "C" void kernel_launch(void* const* d_in, const int* in_sizes, int n_in,
                              void* d_out, int out_size) {
    const float* x          = (const float*)d_in[0];
    const float* ln1_g      = (const float*)d_in[1];
    const float* ln1_b      = (const float*)d_in[2];
    const float* qkv_w      = (const float*)d_in[3];
    const float* qkv_b      = (const float*)d_in[4];
    const float* attn_out_w = (const float*)d_in[5];
    const float* attn_out_b = (const float*)d_in[6];
    const float* ln2_g      = (const float*)d_in[7];
    const float* ln2_b      = (const float*)d_in[8];
    const float* conv_w     = (const float*)d_in[9];
    const float* conv_b     = (const float*)d_in[10];
    const float* ln3_g      = (const float*)d_in[11];
    const float* ln3_b      = (const float*)d_in[12];
    const float* gate_w     = (const float*)d_in[13];
    const float* gate_b     = (const float*)d_in[14];
    const float* expert_w   = (const float*)d_in[15];
    const float* expert_b   = (const float*)d_in[16];
    const float* ff_w1      = (const float*)d_in[17];
    const float* ff_b1      = (const float*)d_in[18];
    const float* ff_w2      = (const float*)d_in[19];
    const float* ff_b2      = (const float*)d_in[20];
    float* out = (float*)d_out;

    float *xln, *xr, *moey;
    __nv_bfloat16 *wh, *wl, *xh, *xl, *qh, *ql, *ah, *al, *xrh, *xrl, *hh, *hl;
    cudaGetSymbolAddress((void**)&xln,  g_xln);
    cudaGetSymbolAddress((void**)&xr,   g_x);
    cudaGetSymbolAddress((void**)&moey, g_moey);
    cudaGetSymbolAddress((void**)&wh,   g_wh);
    cudaGetSymbolAddress((void**)&wl,   g_wl);
    cudaGetSymbolAddress((void**)&xh,   g_xh);
    cudaGetSymbolAddress((void**)&xl,   g_xl);
    cudaGetSymbolAddress((void**)&qh,   g_qkvh);
    cudaGetSymbolAddress((void**)&ql,   g_qkvl);
    cudaGetSymbolAddress((void**)&ah,   g_ah);
    cudaGetSymbolAddress((void**)&al,   g_al);
    cudaGetSymbolAddress((void**)&xrh,  g_xrh);
    cudaGetSymbolAddress((void**)&xrl,  g_xrl);
    cudaGetSymbolAddress((void**)&hh,   g_hh);
    cudaGetSymbolAddress((void**)&hl,   g_hl);

    cudaFuncSetAttribute(gemm_mma<false, false, true>,  cudaFuncAttributeMaxDynamicSharedMemorySize, GEMM_SMEM);
    cudaFuncSetAttribute(gemm_mma<false, true, false>,  cudaFuncAttributeMaxDynamicSharedMemorySize, GEMM_SMEM);
    cudaFuncSetAttribute(gemm_mma<true, false, true>,   cudaFuncAttributeMaxDynamicSharedMemorySize, GEMM_SMEM);
    cudaFuncSetAttribute(gemm_conv, cudaFuncAttributeMaxDynamicSharedMemorySize, GEMM_SMEM);
    cudaFuncSetAttribute(gemm_moe,  cudaFuncAttributeMaxDynamicSharedMemorySize, GEMM_SMEM);

    const dim3 tblk(32, 8);

    // side stream for weight prep (created per call; intentionally leaked —
    // kernel_launch runs only for correctness + capture)
    cudaStream_t sw;
    cudaEvent_t ev_fork, ev_qkvw, ev_wt;
    cudaStreamCreateWithFlags(&sw, cudaStreamNonBlocking);
    cudaEventCreateWithFlags(&ev_fork, cudaEventDisableTiming);
    cudaEventCreateWithFlags(&ev_qkvw, cudaEventDisableTiming);
    cudaEventCreateWithFlags(&ev_wt,   cudaEventDisableTiming);

    // main: LN1 (independent of weights)
    ln_kernel<<<TOK, 256>>>(x, ln1_g, ln1_b, nullptr, xh, xl);
    cudaEventRecord(ev_fork, 0);
    cudaStreamWaitEvent(sw, ev_fork, 0);

    // side stream: all weight transforms (qkv first — it's on the critical path)
    wt_kernel<<<dim3(3072/32, 1024/32), tblk, 0, sw>>>(qkv_w, wh + OFF_QKV, wl + OFF_QKV, 1024, 3072);
    cudaEventRecord(ev_qkvw, sw);
    wt_kernel<<<dim3(1024/32, 1024/32), tblk, 0, sw>>>(attn_out_w, wh + OFF_ATT, wl + OFF_ATT, 1024, 1024);
    convw_t<<<(1024*3072)/256, 256, 0, sw>>>(conv_w, wh + OFF_CONV, wl + OFF_CONV);
    wt_kernel<<<dim3(4096/32, 1024/32), tblk, 0, sw>>>(ff_w1, wh + OFF_FF1, wl + OFF_FF1, 1024, 4096);
    wt_kernel<<<dim3(1024/32, 1024/32, NE), tblk, 0, sw>>>(expert_w, wh + OFF_EXP, wl + OFF_EXP, 1024, 1024);
    wt_kernel<<<dim3(1024/32, 4096/32), tblk, 0, sw>>>(ff_w2, wh + OFF_FF2, wl + OFF_FF2, 4096, 1024);
    cudaEventRecord(ev_wt, sw);

    // main: qkv GEMM as soon as its weights land; attention overlaps the rest
    cudaStreamWaitEvent(0, ev_qkvw, 0);
    gemm_mma<false, false, true><<<dim3(3072/128, TOK/128), 256, GEMM_SMEM>>>(
        xh, xl, wh + OFF_QKV, wl + OFF_QKV, qkv_b, nullptr, nullptr, qh, ql,
        TOK, 3072, 1024);
    attn_tc<<<BB * (LL / WIN) * NH, 256>>>(qh, ql, ah, al);

    // join: all remaining weights must be ready before the proj GEMM
    cudaStreamWaitEvent(0, ev_wt, 0);
    gemm_mma<false, true, false><<<dim3(1024/128, TOK/128), 256, GEMM_SMEM>>>(
        ah, al, wh + OFF_ATT, wl + OFF_ATT, attn_out_b, x, xr, nullptr, nullptr,
        TOK, 1024, 1024);

    // 2) LN2 -> dilated conv GEMM (fused im2col gather, +resid in place)
    ln_kernel<<<TOK, 256>>>(xr, ln2_g, ln2_b, nullptr, xh, xl);
    gemm_conv<<<dim3(1024/128, TOK/128), 256, GEMM_SMEM>>>(
        xh, xl, wh + OFF_CONV, wl + OFF_CONV, conv_b, xr);

    // 3) LN3 -> gate -> sparse top-2 MoE -> combine (emits split resid)
    ln_kernel<<<TOK, 256>>>(xr, ln3_g, ln3_b, xln, xh, xl);
    gate_kernel<<<TOK / 8, 256>>>(xln, gate_w, gate_b);
    scatter_kernel<<<TOK / 256, 256>>>();
    tile_build<<<1, 256>>>();
    gemm_moe<<<dim3(1024/128, MAXTILE), 256, GEMM_SMEM>>>(
        xh, xl, wh + OFF_EXP, wl + OFF_EXP, expert_b, moey);
    combine_kernel<<<TOK, 256>>>(moey, xr, xrh, xrl);

    // 4) FF1 (gelu, split out) -> FF2 (+resid -> out), entropy scalar
    gemm_mma<true, false, true><<<dim3(FFH/128, TOK/128), 256, GEMM_SMEM>>>(
        xrh, xrl, wh + OFF_FF1, wl + OFF_FF1, ff_b1, nullptr, nullptr, hh, hl,
        TOK, FFH, 1024);
    gemm_mma<false, true, false><<<dim3(1024/128, TOK/128), 256, GEMM_SMEM>>>(
        hh, hl, wh + OFF_FF2, wl + OFF_FF2, ff_b2, xr, out, nullptr, nullptr,
        TOK, 1024, FFH);
    ent_reduce<<<1, 256>>>(out + (size_t)TOK * DD);
}